// round 1
// baseline (speedup 1.0000x reference)
#include <cuda_runtime.h>

// Problem constants
#define Bb 4
#define Cc 2048
#define Dd 1024
#define Hh 8
#define Kk 64          // k_size
#define HK 512         // heads * k_size
#define HV 1024        // Mv output cols
#define Vd 128         // v_size per head
#define Uu 256         // C / H

// ---------------------------------------------------------------------------
// Scratch (device globals: allocation-free rule)
// ---------------------------------------------------------------------------
__device__ float g_Pq[Bb * Cc * HK];                 // 16 MB : x @ Mq
__device__ float g_Pk[Bb * Cc * HK];                 // 16 MB : x @ Mk
__device__ float g_Pv[Bb * Cc * HV];                 // 32 MB : x @ Mv
// E[b][h][q%8][c2][q/8] = exp(S[q,c2]/8), laid out for clean stage-3 GEMMs
__device__ float g_E[Bb * Hh * 8 * Cc * Uu];         // 512 MB
__device__ float g_invD[Bb * Hh * Cc];               // 1/sum_q E

// ---------------------------------------------------------------------------
// Kernel 1: projection SGEMM  P[8192, N] = X[8192, 1024] @ W[1024, N]
// 128x128x16 tile, 256 threads, 8x8 microtile
// ---------------------------------------------------------------------------
__global__ __launch_bounds__(256) void k_proj(const float* __restrict__ X,
                                              const float* __restrict__ W,
                                              float* __restrict__ P, int N) {
    __shared__ float As[16][132];   // transposed A tile (k-major), padded
    __shared__ float Bs[16][128];
    const int m0 = blockIdx.y * 128;
    const int n0 = blockIdx.x * 128;
    const int tid = threadIdx.x;
    const int tx = tid & 15, ty = tid >> 4;
    const int a_row = tid >> 2, a_col4 = (tid & 3) << 2;   // A: 128 rows x 16 cols
    const int b_row = tid >> 5, b_col = (tid & 31) << 2;   // B: 16 rows x 128 cols

    float acc[8][8];
#pragma unroll
    for (int i = 0; i < 8; i++)
#pragma unroll
        for (int j = 0; j < 8; j++) acc[i][j] = 0.f;

    for (int k0 = 0; k0 < Dd; k0 += 16) {
#pragma unroll
        for (int r = 0; r < 2; r++) {
            int row = a_row + r * 64;
            float4 v = *(const float4*)(X + (size_t)(m0 + row) * Dd + k0 + a_col4);
            As[a_col4 + 0][row] = v.x;
            As[a_col4 + 1][row] = v.y;
            As[a_col4 + 2][row] = v.z;
            As[a_col4 + 3][row] = v.w;
        }
#pragma unroll
        for (int r = 0; r < 2; r++) {
            int row = b_row + r * 8;
            *(float4*)(&Bs[row][b_col]) =
                *(const float4*)(W + (size_t)(k0 + row) * N + n0 + b_col);
        }
        __syncthreads();
#pragma unroll
        for (int kk = 0; kk < 16; kk++) {
            float4 a0 = *(const float4*)(&As[kk][ty * 8]);
            float4 a1 = *(const float4*)(&As[kk][ty * 8 + 4]);
            float4 b0 = *(const float4*)(&Bs[kk][tx * 8]);
            float4 b1 = *(const float4*)(&Bs[kk][tx * 8 + 4]);
            float a[8] = {a0.x, a0.y, a0.z, a0.w, a1.x, a1.y, a1.z, a1.w};
            float b[8] = {b0.x, b0.y, b0.z, b0.w, b1.x, b1.y, b1.z, b1.w};
#pragma unroll
            for (int i = 0; i < 8; i++)
#pragma unroll
                for (int j = 0; j < 8; j++)
                    acc[i][j] = fmaf(a[i], b[j], acc[i][j]);
        }
        __syncthreads();
    }
#pragma unroll
    for (int i = 0; i < 8; i++) {
        int m = m0 + ty * 8 + i;
#pragma unroll
        for (int j = 0; j < 8; j += 4) {
            float4 v = make_float4(acc[i][j], acc[i][j + 1], acc[i][j + 2], acc[i][j + 3]);
            *(float4*)(P + (size_t)m * N + n0 + tx * 8 + j) = v;
        }
    }
}

// ---------------------------------------------------------------------------
// Kernel 2: per-(b,h) scores.  Qh,Kh = contiguous [2048 x 64] blocks.
// E = exp(Qh . Kh^T / 8), stored as g_E[z][q%8][c2][q/8]
// Tile: 128 (c2) x 128 (q), K=64 in two 32-steps.
// ---------------------------------------------------------------------------
__global__ __launch_bounds__(256) void k_scores() {
    __shared__ float Ks[32][132];   // [k][c2]
    __shared__ float Qs[32][132];   // [k][q]
    const int z = blockIdx.z;             // b*8 + h
    const int c20 = blockIdx.y * 128;
    const int q0 = blockIdx.x * 128;
    const float* Qh = g_Pq + (size_t)z * (Cc * Kk);
    const float* Kh = g_Pk + (size_t)z * (Cc * Kk);
    const int tid = threadIdx.x;
    const int tx = tid & 15, ty = tid >> 4;
    const int l_row = tid >> 3;             // 0..31
    const int l_col = (tid & 7) << 2;       // k offset 0..28

    float acc[8][8];
#pragma unroll
    for (int i = 0; i < 8; i++)
#pragma unroll
        for (int j = 0; j < 8; j++) acc[i][j] = 0.f;

    for (int k0 = 0; k0 < Kk; k0 += 32) {
#pragma unroll
        for (int r = 0; r < 4; r++) {
            int row = l_row + r * 32;
            float4 kv = *(const float4*)(Kh + (size_t)(c20 + row) * Kk + k0 + l_col);
            Ks[l_col + 0][row] = kv.x;
            Ks[l_col + 1][row] = kv.y;
            Ks[l_col + 2][row] = kv.z;
            Ks[l_col + 3][row] = kv.w;
            float4 qv = *(const float4*)(Qh + (size_t)(q0 + row) * Kk + k0 + l_col);
            Qs[l_col + 0][row] = qv.x;
            Qs[l_col + 1][row] = qv.y;
            Qs[l_col + 2][row] = qv.z;
            Qs[l_col + 3][row] = qv.w;
        }
        __syncthreads();
#pragma unroll
        for (int kk = 0; kk < 32; kk++) {
            float4 a0 = *(const float4*)(&Ks[kk][ty * 8]);
            float4 a1 = *(const float4*)(&Ks[kk][ty * 8 + 4]);
            float4 b0 = *(const float4*)(&Qs[kk][tx * 8]);
            float4 b1 = *(const float4*)(&Qs[kk][tx * 8 + 4]);
            float a[8] = {a0.x, a0.y, a0.z, a0.w, a1.x, a1.y, a1.z, a1.w};
            float b[8] = {b0.x, b0.y, b0.z, b0.w, b1.x, b1.y, b1.z, b1.w};
#pragma unroll
            for (int i = 0; i < 8; i++)
#pragma unroll
                for (int j = 0; j < 8; j++)
                    acc[i][j] = fmaf(a[i], b[j], acc[i][j]);
        }
        __syncthreads();
    }

    // epilogue: exp + scatter into [z][j=q%8][c2][u1=q/8]
    const size_t Ebase = (size_t)z * 8 * Cc * Uu;
    const int u1 = (q0 >> 3) + tx;          // q = q0 + tx*8 + j
#pragma unroll
    for (int i = 0; i < 8; i++) {
        int c2 = c20 + ty * 8 + i;
#pragma unroll
        for (int j = 0; j < 8; j++) {
            float e = __expf(acc[i][j] * 0.125f);
            g_E[Ebase + ((size_t)j * Cc + c2) * Uu + u1] = e;
        }
    }
}

// ---------------------------------------------------------------------------
// Kernel 3: invD[z][c2] = 1 / sum_q E.  One warp per c2.
// ---------------------------------------------------------------------------
__global__ __launch_bounds__(256) void k_stats() {
    const int z = blockIdx.y;
    const int warp = threadIdx.x >> 5, lane = threadIdx.x & 31;
    const int c2 = blockIdx.x * 8 + warp;
    const float* base = g_E + (size_t)z * 8 * Cc * Uu + (size_t)c2 * Uu;
    float s = 0.f;
#pragma unroll
    for (int hp = 0; hp < 8; hp++) {
        const float* p = base + (size_t)hp * Cc * Uu;
#pragma unroll
        for (int u = 0; u < Uu; u += 32) s += p[u + lane];
    }
#pragma unroll
    for (int o = 16; o; o >>= 1) s += __shfl_xor_sync(0xffffffffu, s, o);
    if (lane == 0) g_invD[z * Cc + c2] = 1.0f / s;
}

// ---------------------------------------------------------------------------
// Kernel 4: out GEMM per (b,h,h'):  out[256x128] = (E2 * invD)^T @ Vsub
// E2 = g_E[w] : [2048 c2 x 256 u1] (k-major, perfect TN layout)
// Vsub = g_Pv block for (b,h') reinterpreted [2048 c2 x 128 d] (contiguous)
// ---------------------------------------------------------------------------
__global__ __launch_bounds__(256) void k_out(float* __restrict__ out) {
    __shared__ float As[16][132];   // [k][u1], direct (A already k-major)
    __shared__ float Bs[16][128];   // [k][d]
    const int w = blockIdx.y;        // (b*8+h)*8 + hp
    const int u10 = blockIdx.x * 128;
    const int b = w >> 6;
    const int h = (w >> 3) & 7;
    const int hp = w & 7;
    const int z = w >> 3;
    const float* A = g_E + (size_t)w * Cc * Uu;
    const float* Bv = g_Pv + (size_t)b * Cc * HV + (size_t)hp * Uu * HV;
    const float* iD = g_invD + z * Cc;
    const int tid = threadIdx.x;
    const int tx = tid & 15, ty = tid >> 4;
    const int row8 = tid >> 5;             // 0..7
    const int col = (tid & 31) << 2;       // 0..124

    float acc[8][8];
#pragma unroll
    for (int i = 0; i < 8; i++)
#pragma unroll
        for (int j = 0; j < 8; j++) acc[i][j] = 0.f;

    for (int k0 = 0; k0 < Cc; k0 += 16) {
#pragma unroll
        for (int r = 0; r < 2; r++) {
            int row = row8 + r * 8;
            float s = iD[k0 + row];
            float4 av = *(const float4*)(A + (size_t)(k0 + row) * Uu + u10 + col);
            av.x *= s; av.y *= s; av.z *= s; av.w *= s;
            *(float4*)(&As[row][col]) = av;
            *(float4*)(&Bs[row][col]) =
                *(const float4*)(Bv + (size_t)(k0 + row) * Vd + col);
        }
        __syncthreads();
#pragma unroll
        for (int kk = 0; kk < 16; kk++) {
            float4 a0 = *(const float4*)(&As[kk][ty * 8]);
            float4 a1 = *(const float4*)(&As[kk][ty * 8 + 4]);
            float4 b0 = *(const float4*)(&Bs[kk][tx * 8]);
            float4 b1 = *(const float4*)(&Bs[kk][tx * 8 + 4]);
            float a[8] = {a0.x, a0.y, a0.z, a0.w, a1.x, a1.y, a1.z, a1.w};
            float bb[8] = {b0.x, b0.y, b0.z, b0.w, b1.x, b1.y, b1.z, b1.w};
#pragma unroll
            for (int i = 0; i < 8; i++)
#pragma unroll
                for (int j = 0; j < 8; j++)
                    acc[i][j] = fmaf(a[i], bb[j], acc[i][j]);
        }
        __syncthreads();
    }

#pragma unroll
    for (int i = 0; i < 8; i++) {
        int rowo = h * Uu + u10 + ty * 8 + i;
#pragma unroll
        for (int j = 0; j < 8; j += 4) {
            float4 v = make_float4(acc[i][j], acc[i][j + 1], acc[i][j + 2], acc[i][j + 3]);
            *(float4*)(out + ((size_t)b * Cc + rowo) * HV + hp * Vd + tx * 8 + j) = v;
        }
    }
}

// ---------------------------------------------------------------------------
extern "C" void kernel_launch(void* const* d_in, const int* in_sizes, int n_in,
                              void* d_out, int out_size) {
    (void)in_sizes; (void)n_in; (void)out_size;
    const float* x  = (const float*)d_in[0];
    const float* Mq = (const float*)d_in[1];
    const float* Mk = (const float*)d_in[2];
    const float* Mv = (const float*)d_in[3];
    float* out = (float*)d_out;

    float *pq, *pk, *pv;
    cudaGetSymbolAddress((void**)&pq, g_Pq);
    cudaGetSymbolAddress((void**)&pk, g_Pk);
    cudaGetSymbolAddress((void**)&pv, g_Pv);

    dim3 blk(256);
    k_proj<<<dim3(HK / 128, (Bb * Cc) / 128), blk>>>(x, Mq, pq, HK);
    k_proj<<<dim3(HK / 128, (Bb * Cc) / 128), blk>>>(x, Mk, pk, HK);
    k_proj<<<dim3(HV / 128, (Bb * Cc) / 128), blk>>>(x, Mv, pv, HV);
    k_scores<<<dim3(16, 16, 32), blk>>>();
    k_stats<<<dim3(Cc / 8, Bb * Hh), blk>>>();
    k_out<<<dim3(2, 256), blk>>>(out);
}

// round 3
// speedup vs baseline: 2.2168x; 2.2168x over previous
#include <cuda_runtime.h>
#include <cstdint>

#define Bb 4
#define Cc 2048
#define Dd 1024
#define Hh 8
#define Kk 64
#define HK 512
#define HV 1024
#define Vd 128
#define Uu 256

#define PADA 133
#define PADB 132

// ---------------------------------------------------------------------------
// Scratch
// ---------------------------------------------------------------------------
__device__ float g_Pq[(size_t)Bb * Cc * HK];
__device__ float g_Pk[(size_t)Bb * Cc * HK];
__device__ float g_Pv[(size_t)Bb * Cc * HV];
__device__ float g_E[(size_t)Bb * Hh * 8 * Uu * Cc];   // [w][u1][c2]
__device__ float g_D[Bb * Hh * Cc];
__device__ float g_invD[Bb * Hh * Cc];

// ---------------------------------------------------------------------------
__device__ __forceinline__ uint32_t tf32r(float x) {
    uint32_t u;
    asm("cvt.rn.tf32.f32 %0, %1;" : "=r"(u) : "f"(x));
    return u;
}

__device__ __forceinline__ void mma8(float* c, const uint32_t* a, const uint32_t* b) {
    asm volatile(
        "mma.sync.aligned.m16n8k8.row.col.f32.tf32.tf32.f32 "
        "{%0,%1,%2,%3}, {%4,%5,%6,%7}, {%8,%9}, {%0,%1,%2,%3};"
        : "+f"(c[0]), "+f"(c[1]), "+f"(c[2]), "+f"(c[3])
        : "r"(a[0]), "r"(a[1]), "r"(a[2]), "r"(a[3]), "r"(b[0]), "r"(b[1]));
}

// Transposing fill: global [128 rows m][32 cols k] (row-major, ld) ->
// smem As[k][m] pad PADA, tf32-rounded, optional per-k scale. 256 threads.
template <bool SCALED>
__device__ __forceinline__ void fillT(const float* __restrict__ g, int ld,
                                      const float* __restrict__ sc,
                                      float* __restrict__ As, int tid) {
    const int m = tid >> 3;
    const int k4 = (tid & 7) << 2;
    float4 s4 = make_float4(1.f, 1.f, 1.f, 1.f);
    if (SCALED) s4 = *(const float4*)(sc + k4);
#pragma unroll
    for (int p = 0; p < 4; p++) {
        int row = m + p * 32;
        float4 v = *(const float4*)(g + (size_t)row * ld + k4);
        if (SCALED) { v.x *= s4.x; v.y *= s4.y; v.z *= s4.z; v.w *= s4.w; }
        As[(k4 + 0) * PADA + row] = __uint_as_float(tf32r(v.x));
        As[(k4 + 1) * PADA + row] = __uint_as_float(tf32r(v.y));
        As[(k4 + 2) * PADA + row] = __uint_as_float(tf32r(v.z));
        As[(k4 + 3) * PADA + row] = __uint_as_float(tf32r(v.w));
    }
}

// Direct fill: global [32 rows k][128 cols n] (row-major, ld) ->
// smem Bs[k][n] pad PADB, tf32-rounded. 256 threads, float4 stores.
__device__ __forceinline__ void fillD(const float* __restrict__ g, int ld,
                                      float* __restrict__ Bs, int tid) {
    const int kr = tid >> 5;
    const int n4 = (tid & 31) << 2;
#pragma unroll
    for (int p = 0; p < 4; p++) {
        int row = kr + p * 8;
        float4 v = *(const float4*)(g + (size_t)row * ld + n4);
        v.x = __uint_as_float(tf32r(v.x));
        v.y = __uint_as_float(tf32r(v.y));
        v.z = __uint_as_float(tf32r(v.z));
        v.w = __uint_as_float(tf32r(v.w));
        *(float4*)(&Bs[row * PADB + n4]) = v;
    }
}

// One 32-deep k-tile of warp-level mma: warp tile 32(m) x 64(n).
template <int PB>
__device__ __forceinline__ void warp_mma(const float* __restrict__ As,
                                         const float* __restrict__ Bs,
                                         float acc[2][8][4],
                                         int wy, int wx, int lane) {
    const int tg = lane & 3, rr = lane >> 2;
#pragma unroll
    for (int ks = 0; ks < 4; ks++) {
        const int kb = ks * 8;
        uint32_t a[2][4], b[8][2];
#pragma unroll
        for (int mf = 0; mf < 2; mf++) {
            int m = wy * 32 + mf * 16;
            a[mf][0] = __float_as_uint(As[(kb + tg) * PADA + m + rr]);
            a[mf][1] = __float_as_uint(As[(kb + tg) * PADA + m + rr + 8]);
            a[mf][2] = __float_as_uint(As[(kb + 4 + tg) * PADA + m + rr]);
            a[mf][3] = __float_as_uint(As[(kb + 4 + tg) * PADA + m + rr + 8]);
        }
#pragma unroll
        for (int nf = 0; nf < 8; nf++) {
            int n = wx * 64 + nf * 8;
            b[nf][0] = __float_as_uint(Bs[(kb + tg) * PB + n + rr]);
            b[nf][1] = __float_as_uint(Bs[(kb + 4 + tg) * PB + n + rr]);
        }
#pragma unroll
        for (int mf = 0; mf < 2; mf++)
#pragma unroll
            for (int nf = 0; nf < 8; nf++)
                mma8(acc[mf][nf], a[mf], b[nf]);
    }
}

// ---------------------------------------------------------------------------
// Kernel 1: projection GEMM  P[8192,N] = X[8192,1024] @ W[1024,N]
// ---------------------------------------------------------------------------
__global__ __launch_bounds__(256) void k_proj(const float* __restrict__ X,
                                              const float* __restrict__ W,
                                              float* __restrict__ P, int N) {
    __shared__ float As[32 * PADA];
    __shared__ float Bs[32 * PADB];
    const int tid = threadIdx.x, lane = tid & 31, wid = tid >> 5;
    const int wy = wid & 3, wx = wid >> 2;
    const int m0 = blockIdx.y * 128, n0 = blockIdx.x * 128;

    float acc[2][8][4];
#pragma unroll
    for (int i = 0; i < 2; i++)
#pragma unroll
        for (int j = 0; j < 8; j++)
#pragma unroll
            for (int c = 0; c < 4; c++) acc[i][j][c] = 0.f;

    for (int k0 = 0; k0 < Dd; k0 += 32) {
        if (k0) __syncthreads();
        fillT<false>(X + (size_t)m0 * Dd + k0, Dd, nullptr, As, tid);
        fillD(W + (size_t)k0 * N + n0, N, Bs, tid);
        __syncthreads();
        warp_mma<PADB>(As, Bs, acc, wy, wx, lane);
    }

    const int tg = lane & 3, rr = lane >> 2;
#pragma unroll
    for (int mf = 0; mf < 2; mf++) {
        int m = m0 + wy * 32 + mf * 16 + rr;
#pragma unroll
        for (int nf = 0; nf < 8; nf++) {
            int n = n0 + wx * 64 + nf * 8 + tg * 2;
            *(float2*)(P + (size_t)m * N + n) =
                make_float2(acc[mf][nf][0], acc[mf][nf][1]);
            *(float2*)(P + (size_t)(m + 8) * N + n) =
                make_float2(acc[mf][nf][2], acc[mf][nf][3]);
        }
    }
}

// ---------------------------------------------------------------------------
// Kernel 2: scores.  S[c2][q] = Kh . Qh^T ; E = exp(S/8) -> g_E[w][u1][c2],
// fused per-c2 column sums into g_D via atomics.
// ---------------------------------------------------------------------------
__global__ __launch_bounds__(256) void k_scores() {
    __shared__ float As[32 * PADA];
    __shared__ float Bs[32 * PADA];     // transpose-filled: pad 133
    const int tid = threadIdx.x, lane = tid & 31, wid = tid >> 5;
    const int wy = wid & 3, wx = wid >> 2;
    const int z = blockIdx.z;
    const int c20 = blockIdx.y * 128, q0 = blockIdx.x * 128;
    const float* Kh = g_Pk + (size_t)z * Cc * Kk;
    const float* Qh = g_Pq + (size_t)z * Cc * Kk;

    float acc[2][8][4];
#pragma unroll
    for (int i = 0; i < 2; i++)
#pragma unroll
        for (int j = 0; j < 8; j++)
#pragma unroll
            for (int c = 0; c < 4; c++) acc[i][j][c] = 0.f;

    for (int k0 = 0; k0 < Kk; k0 += 32) {
        if (k0) __syncthreads();
        fillT<false>(Kh + (size_t)c20 * Kk + k0, Kk, nullptr, As, tid);  // M=c2
        fillT<false>(Qh + (size_t)q0 * Kk + k0, Kk, nullptr, Bs, tid);   // N=q
        __syncthreads();
        warp_mma<PADA>(As, Bs, acc, wy, wx, lane);
    }

    const int tg = lane & 3, rr = lane >> 2;
    const size_t zb = (size_t)z * 8;
    float rs[2][2] = {{0.f, 0.f}, {0.f, 0.f}};
#pragma unroll
    for (int mf = 0; mf < 2; mf++) {
#pragma unroll
        for (int nf = 0; nf < 8; nf++) {
#pragma unroll
            for (int c = 0; c < 4; c++) {
                int q = q0 + wx * 64 + nf * 8 + tg * 2 + (c & 1);
                int c2 = c20 + wy * 32 + mf * 16 + rr + ((c >> 1) << 3);
                float e = __expf(acc[mf][nf][c] * 0.125f);
                rs[mf][c >> 1] += e;
                g_E[((zb + (q & 7)) * Uu + (q >> 3)) * Cc + c2] = e;
            }
        }
    }
#pragma unroll
    for (int mf = 0; mf < 2; mf++)
#pragma unroll
        for (int h2 = 0; h2 < 2; h2++) {
            float s = rs[mf][h2];
            s += __shfl_xor_sync(0xffffffffu, s, 1);
            s += __shfl_xor_sync(0xffffffffu, s, 2);
            if (tg == 0)
                atomicAdd(&g_D[z * Cc + c20 + wy * 32 + mf * 16 + h2 * 8 + rr], s);
        }
}

// ---------------------------------------------------------------------------
__global__ void k_recip() {
    int i = blockIdx.x * 256 + threadIdx.x;
    g_invD[i] = 1.0f / g_D[i];
}

// ---------------------------------------------------------------------------
// Kernel 3: output GEMM per w=(z*8+hp):
//   O[u1][d] = sum_c2 (E[w][u1][c2]*invD[z][c2]) * V[b,hp][c2][d]
// ---------------------------------------------------------------------------
__global__ __launch_bounds__(256) void k_out(float* __restrict__ out) {
    __shared__ float As[32 * PADA];
    __shared__ float Bs[32 * PADB];
    const int tid = threadIdx.x, lane = tid & 31, wid = tid >> 5;
    const int wy = wid & 3, wx = wid >> 2;
    const int w = blockIdx.y;
    const int u10 = blockIdx.x * 128;
    const int b = w >> 6, h = (w >> 3) & 7, hp = w & 7, z = w >> 3;
    const float* A = g_E + ((size_t)w * Uu + u10) * Cc;
    const float* Bv = g_Pv + (size_t)b * Cc * HV + (size_t)hp * Uu * HV;  // [2048][128]
    const float* iD = g_invD + z * Cc;

    float acc[2][8][4];
#pragma unroll
    for (int i = 0; i < 2; i++)
#pragma unroll
        for (int j = 0; j < 8; j++)
#pragma unroll
            for (int c = 0; c < 4; c++) acc[i][j][c] = 0.f;

    for (int k0 = 0; k0 < Cc; k0 += 32) {
        if (k0) __syncthreads();
        fillT<true>(A + k0, Cc, iD + k0, As, tid);          // M=u1, scaled
        fillD(Bv + (size_t)k0 * Vd, Vd, Bs, tid);           // N=d
        __syncthreads();
        warp_mma<PADB>(As, Bs, acc, wy, wx, lane);
    }

    const int tg = lane & 3, rr = lane >> 2;
#pragma unroll
    for (int mf = 0; mf < 2; mf++) {
        int u1 = u10 + wy * 32 + mf * 16 + rr;
        float* g0 = out + ((size_t)b * Cc + h * Uu + u1) * HV + hp * Vd;
        float* g1 = g0 + 8 * HV;
#pragma unroll
        for (int nf = 0; nf < 8; nf++) {
            int n = wx * 64 + nf * 8 + tg * 2;
            *(float2*)(g0 + n) = make_float2(acc[mf][nf][0], acc[mf][nf][1]);
            *(float2*)(g1 + n) = make_float2(acc[mf][nf][2], acc[mf][nf][3]);
        }
    }
}

// ---------------------------------------------------------------------------
extern "C" void kernel_launch(void* const* d_in, const int* in_sizes, int n_in,
                              void* d_out, int out_size) {
    (void)in_sizes; (void)n_in; (void)out_size;
    const float* x  = (const float*)d_in[0];
    const float* Mq = (const float*)d_in[1];
    const float* Mk = (const float*)d_in[2];
    const float* Mv = (const float*)d_in[3];
    float* out = (float*)d_out;

    float *pPq, *pPk, *pPv, *pD;
    cudaGetSymbolAddress((void**)&pPq, g_Pq);
    cudaGetSymbolAddress((void**)&pPk, g_Pk);
    cudaGetSymbolAddress((void**)&pPv, g_Pv);
    cudaGetSymbolAddress((void**)&pD, g_D);

    cudaMemsetAsync(pD, 0, sizeof(float) * Bb * Hh * Cc);

    k_proj<<<dim3(HK / 128, (Bb * Cc) / 128), 256>>>(x, Mq, pPq, HK);
    k_proj<<<dim3(HK / 128, (Bb * Cc) / 128), 256>>>(x, Mk, pPk, HK);
    k_proj<<<dim3(HV / 128, (Bb * Cc) / 128), 256>>>(x, Mv, pPv, HV);
    k_scores<<<dim3(Cc / 128, Cc / 128, Bb * Hh), 256>>>();
    k_recip<<<(Bb * Hh * Cc) / 256, 256>>>();
    k_out<<<dim3(Uu / 128, Bb * Hh * 8), 256>>>(out);
}

// round 4
// speedup vs baseline: 2.8066x; 1.2660x over previous
#include <cuda_runtime.h>
#include <cuda_fp16.h>
#include <cstdint>

#define Bb 4
#define Cc 2048
#define Dd 1024
#define Kk 64
#define HK 512
#define HV 1024
#define Vd 128
#define Uu 256

#define KT 64                 // k-tile depth
#define STH 72                // smem row stride (halves) -> conflict-free frags
#define TILEH (128 * STH)     // halves per 128-row tile buffer

// ---------------------------------------------------------------------------
// Scratch
// ---------------------------------------------------------------------------
__device__ float g_Pq[(size_t)Bb * Cc * HK];
__device__ float g_Pk[(size_t)Bb * Cc * HK];
__device__ float g_Pv[(size_t)Bb * Cc * HV];
__device__ __align__(16) __half g_E[(size_t)Bb * 8 * 8 * Uu * Cc];  // [w][u1][c2]
__device__ float g_D[Bb * 8 * Cc];
__device__ float g_invD[Bb * 8 * Cc];

// ---------------------------------------------------------------------------
__device__ __forceinline__ uint32_t pack2(float x, float y) {
    __half2 h = __floats2half2_rn(x, y);
    return *reinterpret_cast<uint32_t*>(&h);
}

__device__ __forceinline__ void mma16(float* c, const uint32_t* a, const uint32_t* b) {
    asm volatile(
        "mma.sync.aligned.m16n8k16.row.col.f32.f16.f16.f32 "
        "{%0,%1,%2,%3}, {%4,%5,%6,%7}, {%8,%9}, {%0,%1,%2,%3};"
        : "+f"(c[0]), "+f"(c[1]), "+f"(c[2]), "+f"(c[3])
        : "r"(a[0]), "r"(a[1]), "r"(a[2]), "r"(a[3]), "r"(b[0]), "r"(b[1]));
}

// 64-deep k-tile of warp mma: warp tile 32(m) x 64(n). As[m][STH], Bs[n][STH].
__device__ __forceinline__ void warp_mma64(const __half* As, const __half* Bs,
                                           float acc[2][8][4],
                                           int wy, int wx, int lane) {
    const int tg = lane & 3, rr = lane >> 2;
    const uint32_t* Au = (const uint32_t*)As;
    const uint32_t* Bu = (const uint32_t*)Bs;
    const int ar0 = (wy * 32 + rr) * (STH / 2);
    const int br0 = (wx * 64 + rr) * (STH / 2);
#pragma unroll
    for (int ks = 0; ks < 4; ks++) {
        const int ko = ks * 8 + tg;
        uint32_t a[2][4];
#pragma unroll
        for (int mf = 0; mf < 2; mf++) {
            int base = ar0 + mf * 16 * (STH / 2) + ko;
            a[mf][0] = Au[base];
            a[mf][1] = Au[base + 8 * (STH / 2)];
            a[mf][2] = Au[base + 4];
            a[mf][3] = Au[base + 8 * (STH / 2) + 4];
        }
#pragma unroll
        for (int nf = 0; nf < 8; nf++) {
            int bi = br0 + nf * 8 * (STH / 2) + ko;
            uint32_t b[2] = {Bu[bi], Bu[bi + 4]};
            mma16(acc[0][nf], a[0], b);
            mma16(acc[1][nf], a[1], b);
        }
    }
}

// ---------------------------------------------------------------------------
// Stage/commit helpers (register-staged ping-pong fills)
// ---------------------------------------------------------------------------
struct StA { uint2 v[8]; };      // A: fp32 [128 m][64 k] direct, cvt to half
__device__ __forceinline__ void stageA32(const float* __restrict__ g, int ld,
                                         int tid, StA& s) {
    const int kq = (tid & 15) * 4, r0 = tid >> 4;
#pragma unroll
    for (int p = 0; p < 8; p++) {
        int r = r0 + p * 16;
        float4 v = *(const float4*)(g + (size_t)r * ld + kq);
        s.v[p] = make_uint2(pack2(v.x, v.y), pack2(v.z, v.w));
    }
}
__device__ __forceinline__ void commitA(const StA& s, __half* As, int tid) {
    const int kq = (tid & 15) * 4, r0 = tid >> 4;
#pragma unroll
    for (int p = 0; p < 8; p++)
        *(uint2*)(As + (r0 + p * 16) * STH + kq) = s.v[p];
}

struct StB { uint4 v[4]; };      // B: fp32 [64 k][128 n] -> smem [n][k]
__device__ __forceinline__ void stageBT(const float* __restrict__ g, int ld,
                                        int tid, StB& s) {
    const int n = tid & 127, k8 = (tid >> 7) * 8;
#pragma unroll
    for (int p = 0; p < 4; p++) {
        int kb = k8 + p * 16;
        float f[8];
#pragma unroll
        for (int j = 0; j < 8; j++) f[j] = g[(size_t)(kb + j) * ld + n];
        s.v[p] = make_uint4(pack2(f[0], f[1]), pack2(f[2], f[3]),
                            pack2(f[4], f[5]), pack2(f[6], f[7]));
    }
}
__device__ __forceinline__ void commitB(const StB& s, __half* Bs, int tid) {
    const int n = tid & 127, k8 = (tid >> 7) * 8;
#pragma unroll
    for (int p = 0; p < 4; p++)
        *(uint4*)(Bs + n * STH + k8 + p * 16) = s.v[p];
}

struct StE { uint4 v[4]; };      // A for k_out: half E scaled by invD[k]
__device__ __forceinline__ void stageE(const __half* __restrict__ gE, int ld,
                                       const float* __restrict__ iD,
                                       int tid, StE& s) {
    const int kq = (tid & 7) * 8, r0 = tid >> 3;
    float4 s0 = *(const float4*)(iD + kq);
    float4 s1 = *(const float4*)(iD + kq + 4);
    float sc[8] = {s0.x, s0.y, s0.z, s0.w, s1.x, s1.y, s1.z, s1.w};
#pragma unroll
    for (int p = 0; p < 4; p++) {
        int r = r0 + p * 32;
        uint4 u = *(const uint4*)(gE + (size_t)r * ld + kq);
        const __half2* hp = (const __half2*)&u;
        uint32_t w[4];
#pragma unroll
        for (int q2 = 0; q2 < 4; q2++) {
            float2 f = __half22float2(hp[q2]);
            w[q2] = pack2(f.x * sc[q2 * 2], f.y * sc[q2 * 2 + 1]);
        }
        s.v[p] = make_uint4(w[0], w[1], w[2], w[3]);
    }
}
__device__ __forceinline__ void commitE(const StE& s, __half* As, int tid) {
    const int kq = (tid & 7) * 8, r0 = tid >> 3;
#pragma unroll
    for (int p = 0; p < 4; p++)
        *(uint4*)(As + (r0 + p * 32) * STH + kq) = s.v[p];
}

// Direct fill from half source (k_scores: [128 rows][64 k] half, no cvt)
__device__ __forceinline__ void fillA32_once(const float* __restrict__ g, int ld,
                                             __half* As, int tid) {
    StA s;
    stageA32(g, ld, tid, s);
    commitA(s, As, tid);
}

// ---------------------------------------------------------------------------
// Kernel 1: projection  P[8192,N] = X[8192,1024] @ W[1024,N]  (P fp32)
// ping-pong double buffered, dynamic smem = 4*TILEH halves
// ---------------------------------------------------------------------------
extern __shared__ __align__(16) __half dsm[];

__global__ __launch_bounds__(256) void k_proj(const float* __restrict__ X,
                                              const float* __restrict__ W,
                                              float* __restrict__ P, int N) {
    __half* Abuf[2] = {dsm, dsm + 2 * TILEH};
    __half* Bbuf[2] = {dsm + TILEH, dsm + 3 * TILEH};
    const int tid = threadIdx.x, lane = tid & 31, wid = tid >> 5;
    const int wy = wid & 3, wx = wid >> 2;
    const int m0 = blockIdx.y * 128, n0 = blockIdx.x * 128;

    float acc[2][8][4];
#pragma unroll
    for (int i = 0; i < 2; i++)
#pragma unroll
        for (int j = 0; j < 8; j++)
#pragma unroll
            for (int c = 0; c < 4; c++) acc[i][j][c] = 0.f;

    StA sa; StB sb;
    stageA32(X + (size_t)m0 * Dd, Dd, tid, sa);
    stageBT(W + n0, N, tid, sb);
    commitA(sa, Abuf[0], tid);
    commitB(sb, Bbuf[0], tid);
    __syncthreads();

    const int NIT = Dd / KT;
    for (int it = 0; it < NIT; it++) {
        bool more = (it + 1) < NIT;
        if (more) {
            int k0n = (it + 1) * KT;
            stageA32(X + (size_t)m0 * Dd + k0n, Dd, tid, sa);
            stageBT(W + (size_t)k0n * N + n0, N, tid, sb);
        }
        warp_mma64(Abuf[it & 1], Bbuf[it & 1], acc, wy, wx, lane);
        if (more) {
            commitA(sa, Abuf[(it + 1) & 1], tid);
            commitB(sb, Bbuf[(it + 1) & 1], tid);
        }
        __syncthreads();
    }

    const int tg = lane & 3, rr = lane >> 2;
#pragma unroll
    for (int mf = 0; mf < 2; mf++) {
        int m = m0 + wy * 32 + mf * 16 + rr;
#pragma unroll
        for (int nf = 0; nf < 8; nf++) {
            int n = n0 + wx * 64 + nf * 8 + tg * 2;
            *(float2*)(P + (size_t)m * N + n) =
                make_float2(acc[mf][nf][0], acc[mf][nf][1]);
            *(float2*)(P + (size_t)(m + 8) * N + n) =
                make_float2(acc[mf][nf][2], acc[mf][nf][3]);
        }
    }
}

// ---------------------------------------------------------------------------
// Kernel 2: scores.  S[c2][q] = Kh.Qh^T (K=64, single tile); E=exp(S/8) ->
// g_E[w][u1][c2] (half) via smem transpose; fused column sums -> g_D.
// ---------------------------------------------------------------------------
__global__ __launch_bounds__(256) void k_scores() {
    __shared__ __align__(16) char arena[2 * TILEH * 2];   // 36864 B
    __half* As = (__half*)arena;
    __half* Bs = As + TILEH;
    const int tid = threadIdx.x, lane = tid & 31, wid = tid >> 5;
    const int wy = wid & 3, wx = wid >> 2;
    const int z = blockIdx.z;
    const int c20 = blockIdx.y * 128, q0 = blockIdx.x * 128;
    const float* Kh = g_Pk + (size_t)z * Cc * Kk;
    const float* Qh = g_Pq + (size_t)z * Cc * Kk;

    float acc[2][8][4];
#pragma unroll
    for (int i = 0; i < 2; i++)
#pragma unroll
        for (int j = 0; j < 8; j++)
#pragma unroll
            for (int c = 0; c < 4; c++) acc[i][j][c] = 0.f;

    fillA32_once(Kh + (size_t)c20 * Kk, Kk, As, tid);   // M = c2
    fillA32_once(Qh + (size_t)q0 * Kk, Kk, Bs, tid);    // N = q ([n][k] direct)
    __syncthreads();
    warp_mma64(As, Bs, acc, wy, wx, lane);
    __syncthreads();                       // arena reuse below

    // exp + half-round + transpose-stage + fused D sums
    __half* T = (__half*)arena;            // [128 q][136]
    const int tg = lane & 3, rr = lane >> 2;
    float rs[2][2] = {{0.f, 0.f}, {0.f, 0.f}};
#pragma unroll
    for (int mf = 0; mf < 2; mf++)
#pragma unroll
        for (int nf = 0; nf < 8; nf++)
#pragma unroll
            for (int c = 0; c < 4; c++) {
                int ql = wx * 64 + nf * 8 + tg * 2 + (c & 1);
                int c2l = wy * 32 + mf * 16 + ((c >> 1) << 3) + rr;
                __half h = __float2half_rn(__expf(acc[mf][nf][c] * 0.125f));
                rs[mf][c >> 1] += __half2float(h);
                T[ql * 136 + c2l] = h;
            }
#pragma unroll
    for (int mf = 0; mf < 2; mf++)
#pragma unroll
        for (int h2 = 0; h2 < 2; h2++) {
            float s = rs[mf][h2];
            s += __shfl_xor_sync(0xffffffffu, s, 1);
            s += __shfl_xor_sync(0xffffffffu, s, 2);
            if (tg == 0)
                atomicAdd(&g_D[z * Cc + c20 + wy * 32 + mf * 16 + h2 * 8 + rr], s);
        }
    __syncthreads();

    // coalesced E writeout: 2 threads per q-row, 8 x uint4 each
    const int qrow = tid >> 1, off = (tid & 1) * 64;
    const int q = q0 + qrow;
    __half* gd = g_E + ((size_t)(z * 8 + (q & 7)) * Uu + (q >> 3)) * Cc + c20 + off;
    const uint4* Ts = (const uint4*)(T + qrow * 136 + off);
    uint4* gu = (uint4*)gd;
#pragma unroll
    for (int s = 0; s < 8; s++) gu[s] = Ts[s];
}

// ---------------------------------------------------------------------------
__global__ void k_recip() {
    int i = blockIdx.x * 256 + threadIdx.x;
    g_invD[i] = 1.0f / g_D[i];
}

// ---------------------------------------------------------------------------
// Kernel 3: out GEMM per w: O[u1][d] = sum_c2 (E*invD)[u1][c2] * V[c2][d]
// ping-pong double buffered
// ---------------------------------------------------------------------------
__global__ __launch_bounds__(256) void k_out(float* __restrict__ out) {
    __half* Abuf[2] = {dsm, dsm + 2 * TILEH};
    __half* Bbuf[2] = {dsm + TILEH, dsm + 3 * TILEH};
    const int tid = threadIdx.x, lane = tid & 31, wid = tid >> 5;
    const int wy = wid & 3, wx = wid >> 2;
    const int w = blockIdx.y;
    const int u10 = blockIdx.x * 128;
    const int b = w >> 6, h = (w >> 3) & 7, hp = w & 7, z = w >> 3;
    const __half* A = g_E + ((size_t)w * Uu + u10) * Cc;
    const float* Bv = g_Pv + (size_t)b * Cc * HV + (size_t)hp * Uu * HV;
    const float* iD = g_invD + z * Cc;

    float acc[2][8][4];
#pragma unroll
    for (int i = 0; i < 2; i++)
#pragma unroll
        for (int j = 0; j < 8; j++)
#pragma unroll
            for (int c = 0; c < 4; c++) acc[i][j][c] = 0.f;

    StE se; StB sb;
    stageE(A, Cc, iD, tid, se);
    stageBT(Bv, Vd, tid, sb);
    commitE(se, Abuf[0], tid);
    commitB(sb, Bbuf[0], tid);
    __syncthreads();

    const int NIT = Cc / KT;
    for (int it = 0; it < NIT; it++) {
        bool more = (it + 1) < NIT;
        if (more) {
            int k0n = (it + 1) * KT;
            stageE(A + k0n, Cc, iD + k0n, tid, se);
            stageBT(Bv + (size_t)k0n * Vd, Vd, tid, sb);
        }
        warp_mma64(Abuf[it & 1], Bbuf[it & 1], acc, wy, wx, lane);
        if (more) {
            commitE(se, Abuf[(it + 1) & 1], tid);
            commitB(sb, Bbuf[(it + 1) & 1], tid);
        }
        __syncthreads();
    }

    const int tg = lane & 3, rr = lane >> 2;
#pragma unroll
    for (int mf = 0; mf < 2; mf++) {
        int u1 = u10 + wy * 32 + mf * 16 + rr;
        float* g0 = out + ((size_t)b * Cc + h * Uu + u1) * HV + hp * Vd;
        float* g1 = g0 + (size_t)8 * HV;
#pragma unroll
        for (int nf = 0; nf < 8; nf++) {
            int n = wx * 64 + nf * 8 + tg * 2;
            *(float2*)(g0 + n) = make_float2(acc[mf][nf][0], acc[mf][nf][1]);
            *(float2*)(g1 + n) = make_float2(acc[mf][nf][2], acc[mf][nf][3]);
        }
    }
}

// ---------------------------------------------------------------------------
extern "C" void kernel_launch(void* const* d_in, const int* in_sizes, int n_in,
                              void* d_out, int out_size) {
    (void)in_sizes; (void)n_in; (void)out_size;
    const float* x  = (const float*)d_in[0];
    const float* Mq = (const float*)d_in[1];
    const float* Mk = (const float*)d_in[2];
    const float* Mv = (const float*)d_in[3];
    float* out = (float*)d_out;

    float *pPq, *pPk, *pPv, *pD;
    cudaGetSymbolAddress((void**)&pPq, g_Pq);
    cudaGetSymbolAddress((void**)&pPk, g_Pk);
    cudaGetSymbolAddress((void**)&pPv, g_Pv);
    cudaGetSymbolAddress((void**)&pD, g_D);

    const int DSM = 4 * TILEH * sizeof(__half);   // 73728 B
    static bool attr_done = false;
    if (!attr_done) {
        cudaFuncSetAttribute(k_proj, cudaFuncAttributeMaxDynamicSharedMemorySize, DSM);
        cudaFuncSetAttribute(k_out, cudaFuncAttributeMaxDynamicSharedMemorySize, DSM);
        attr_done = true;
    }

    cudaMemsetAsync(pD, 0, sizeof(float) * Bb * 8 * Cc);

    k_proj<<<dim3(HK / 128, (Bb * Cc) / 128), 256, DSM>>>(x, Mq, pPq, HK);
    k_proj<<<dim3(HK / 128, (Bb * Cc) / 128), 256, DSM>>>(x, Mk, pPk, HK);
    k_proj<<<dim3(HV / 128, (Bb * Cc) / 128), 256, DSM>>>(x, Mv, pPv, HV);
    k_scores<<<dim3(Cc / 128, Cc / 128, Bb * 8), 256>>>();
    k_recip<<<(Bb * 8 * Cc) / 256, 256>>>();
    k_out<<<dim3(Uu / 128, Bb * 8 * 8), 256, DSM>>>(out);
}

// round 6
// speedup vs baseline: 3.2781x; 1.1680x over previous
#include <cuda_runtime.h>
#include <cuda_fp16.h>
#include <cstdint>

#define Bb 4
#define Cc 2048
#define Dd 1024
#define Kk 64
#define HK 512
#define HV 1024
#define Vd 128
#define Uu 256

#define KT 64
#define STH 72                  // smem stride (halves) for 64-k tiles
#define TILEH (128 * STH)       // halves per 128-row tile
#define VSTH 136                // smem stride (halves) for 128-k V tile

// ---------------------------------------------------------------------------
// Scratch
// ---------------------------------------------------------------------------
__device__ float g_Pq[(size_t)Bb * Cc * HK];
__device__ float g_Pk[(size_t)Bb * Cc * HK];
__device__ float g_Pv[(size_t)Bb * Cc * HV];
__device__ float g_invD[Bb * 8 * Cc];

// ---------------------------------------------------------------------------
__device__ __forceinline__ uint32_t pack2(float x, float y) {
    __half2 h = __floats2half2_rn(x, y);
    return *reinterpret_cast<uint32_t*>(&h);
}

__device__ __forceinline__ void mma16(float* c, const uint32_t* a, const uint32_t* b) {
    asm volatile(
        "mma.sync.aligned.m16n8k16.row.col.f32.f16.f16.f32 "
        "{%0,%1,%2,%3}, {%4,%5,%6,%7}, {%8,%9}, {%0,%1,%2,%3};"
        : "+f"(c[0]), "+f"(c[1]), "+f"(c[2]), "+f"(c[3])
        : "r"(a[0]), "r"(a[1]), "r"(a[2]), "r"(a[3]), "r"(b[0]), "r"(b[1]));
}

__device__ __forceinline__ void ldm4(uint32_t* r, uint32_t addr) {
    asm volatile(
        "ldmatrix.sync.aligned.m8n8.x4.shared.b16 {%0,%1,%2,%3}, [%4];"
        : "=r"(r[0]), "=r"(r[1]), "=r"(r[2]), "=r"(r[3]) : "r"(addr));
}

__device__ __forceinline__ uint32_t s2u(const void* p) {
    return (uint32_t)__cvta_generic_to_shared(p);
}

// 64-deep k-tile warp mma via ldmatrix: warp tile 32(m) x 64(n).
// As[m][STH] halves; Bs[n][SB] halves.
template <int SB>
__device__ __forceinline__ void warp_mma64(const __half* As, const __half* Bs,
                                           float acc[2][8][4],
                                           int wy, int wx, int lane) {
    const uint32_t ab = s2u(As), bb = s2u(Bs);
    const int arow = wy * 32 + (lane & 15);
    const int kA = (lane >> 4) << 3;               // A k-half select
    const int brow = wx * 64 + (lane & 7) + ((lane >> 4) << 3);
    const int kB = ((lane >> 3) & 1) << 3;         // B k-half select
#pragma unroll
    for (int ks = 0; ks < 4; ks++) {
        uint32_t a[2][4];
        ldm4(a[0], ab + (uint32_t)((arow * STH + ks * 16 + kA) * 2));
        ldm4(a[1], ab + (uint32_t)(((arow + 16) * STH + ks * 16 + kA) * 2));
#pragma unroll
        for (int j = 0; j < 4; j++) {
            uint32_t b[4];
            ldm4(b, bb + (uint32_t)(((brow + j * 16) * SB + ks * 16 + kB) * 2));
            mma16(acc[0][2 * j], a[0], b);
            mma16(acc[0][2 * j + 1], a[0], b + 2);
            mma16(acc[1][2 * j], a[1], b);
            mma16(acc[1][2 * j + 1], a[1], b + 2);
        }
    }
}

// ---------------------------------------------------------------------------
// Stage/commit fills
// ---------------------------------------------------------------------------
struct StA { uint2 v[8]; };      // fp32 [128 m][64 k] direct, cvt to half
__device__ __forceinline__ void stageA32(const float* __restrict__ g, int ld,
                                         int tid, StA& s) {
    const int kq = (tid & 15) * 4, r0 = tid >> 4;
#pragma unroll
    for (int p = 0; p < 8; p++) {
        int r = r0 + p * 16;
        float4 v = *(const float4*)(g + (size_t)r * ld + kq);
        s.v[p] = make_uint2(pack2(v.x, v.y), pack2(v.z, v.w));
    }
}
__device__ __forceinline__ void commitA(const StA& s, __half* As, int tid) {
    const int kq = (tid & 15) * 4, r0 = tid >> 4;
#pragma unroll
    for (int p = 0; p < 8; p++)
        *(uint2*)(As + (r0 + p * 16) * STH + kq) = s.v[p];
}
__device__ __forceinline__ void fillA32_once(const float* __restrict__ g, int ld,
                                             __half* As, int tid) {
    StA s;
    stageA32(g, ld, tid, s);
    commitA(s, As, tid);
}

struct StB { uint4 v[4]; };      // fp32 [64 k][128 n] -> smem [n][k]
__device__ __forceinline__ void stageBT(const float* __restrict__ g, int ld,
                                        int tid, StB& s) {
    const int n = tid & 127, k8 = (tid >> 7) * 8;
#pragma unroll
    for (int p = 0; p < 4; p++) {
        int kb = k8 + p * 16;
        float f[8];
#pragma unroll
        for (int j = 0; j < 8; j++) f[j] = g[(size_t)(kb + j) * ld + n];
        s.v[p] = make_uint4(pack2(f[0], f[1]), pack2(f[2], f[3]),
                            pack2(f[4], f[5]), pack2(f[6], f[7]));
    }
}
__device__ __forceinline__ void commitB(const StB& s, __half* Bs, int tid) {
    const int n = tid & 127, k8 = (tid >> 7) * 8;
#pragma unroll
    for (int p = 0; p < 4; p++)
        *(uint4*)(Bs + n * STH + k8 + p * 16) = s.v[p];
}

// ---------------------------------------------------------------------------
// Kernel 1: projection  P[8192,N] = X[8192,1024] @ W[1024,N]  (P fp32)
// ---------------------------------------------------------------------------
extern __shared__ __align__(16) __half dsm[];

__global__ __launch_bounds__(256) void k_proj(const float* __restrict__ X,
                                              const float* __restrict__ W,
                                              float* __restrict__ P, int N) {
    __half* Abuf[2] = {dsm, dsm + 2 * TILEH};
    __half* Bbuf[2] = {dsm + TILEH, dsm + 3 * TILEH};
    const int tid = threadIdx.x, lane = tid & 31, wid = tid >> 5;
    const int wy = wid & 3, wx = wid >> 2;
    const int m0 = blockIdx.y * 128, n0 = blockIdx.x * 128;

    float acc[2][8][4];
#pragma unroll
    for (int i = 0; i < 2; i++)
#pragma unroll
        for (int j = 0; j < 8; j++)
#pragma unroll
            for (int c = 0; c < 4; c++) acc[i][j][c] = 0.f;

    StA sa; StB sb;
    stageA32(X + (size_t)m0 * Dd, Dd, tid, sa);
    stageBT(W + n0, N, tid, sb);
    commitA(sa, Abuf[0], tid);
    commitB(sb, Bbuf[0], tid);
    __syncthreads();

    const int NIT = Dd / KT;
    for (int it = 0; it < NIT; it++) {
        bool more = (it + 1) < NIT;
        if (more) {
            int k0n = (it + 1) * KT;
            stageA32(X + (size_t)m0 * Dd + k0n, Dd, tid, sa);
            stageBT(W + (size_t)k0n * N + n0, N, tid, sb);
        }
        warp_mma64<STH>(Abuf[it & 1], Bbuf[it & 1], acc, wy, wx, lane);
        if (more) {
            commitA(sa, Abuf[(it + 1) & 1], tid);
            commitB(sb, Bbuf[(it + 1) & 1], tid);
        }
        __syncthreads();
    }

    const int tg = lane & 3, rr = lane >> 2;
#pragma unroll
    for (int mf = 0; mf < 2; mf++) {
        int m = m0 + wy * 32 + mf * 16 + rr;
#pragma unroll
        for (int nf = 0; nf < 8; nf++) {
            int n = n0 + wx * 64 + nf * 8 + tg * 2;
            *(float2*)(P + (size_t)m * N + n) =
                make_float2(acc[mf][nf][0], acc[mf][nf][1]);
            *(float2*)(P + (size_t)(m + 8) * N + n) =
                make_float2(acc[mf][nf][2], acc[mf][nf][3]);
        }
    }
}

// ---------------------------------------------------------------------------
// Kernel 2: column sums.  invD[z][c2] = 1 / sum_q exp((K[c2].Q[q])/8)
// One CTA per (z, c2-tile of 128); loops all 16 q-tiles; K tile resident.
// FIX vs R5: wx=0/1 warps cover disjoint q-halves -> combine partials via
// smem atomics instead of racing direct stores.
// ---------------------------------------------------------------------------
__global__ __launch_bounds__(256) void k_sums() {
    __shared__ __align__(16) __half As[TILEH];   // K tile [c2][k]
    __shared__ __align__(16) __half Bs[TILEH];   // Q tile [q][k]
    __shared__ float sD[128];
    const int tid = threadIdx.x, lane = tid & 31, wid = tid >> 5;
    const int wy = wid & 3, wx = wid >> 2;
    const int tg = lane & 3, rr = lane >> 2;
    const int z = blockIdx.y;
    const int c20 = blockIdx.x * 128;
    const float* Kh = g_Pk + (size_t)z * Cc * Kk;
    const float* Qh = g_Pq + (size_t)z * Cc * Kk;

    if (tid < 128) sD[tid] = 0.f;
    fillA32_once(Kh + (size_t)c20 * Kk, Kk, As, tid);

    float rs[2][2] = {{0.f, 0.f}, {0.f, 0.f}};
    for (int qt = 0; qt < Cc / 128; qt++) {
        if (qt) __syncthreads();
        fillA32_once(Qh + (size_t)qt * 128 * Kk, Kk, Bs, tid);
        __syncthreads();
        float acc[2][8][4];
#pragma unroll
        for (int i = 0; i < 2; i++)
#pragma unroll
            for (int j = 0; j < 8; j++)
#pragma unroll
                for (int c = 0; c < 4; c++) acc[i][j][c] = 0.f;
        warp_mma64<STH>(As, Bs, acc, wy, wx, lane);
#pragma unroll
        for (int mf = 0; mf < 2; mf++)
#pragma unroll
            for (int nf = 0; nf < 8; nf++) {
                rs[mf][0] += __expf(acc[mf][nf][0] * 0.125f)
                           + __expf(acc[mf][nf][1] * 0.125f);
                rs[mf][1] += __expf(acc[mf][nf][2] * 0.125f)
                           + __expf(acc[mf][nf][3] * 0.125f);
            }
    }
#pragma unroll
    for (int mf = 0; mf < 2; mf++)
#pragma unroll
        for (int h2 = 0; h2 < 2; h2++) {
            float s = rs[mf][h2];
            s += __shfl_xor_sync(0xffffffffu, s, 1);
            s += __shfl_xor_sync(0xffffffffu, s, 2);
            if (tg == 0)
                atomicAdd(&sD[wy * 32 + mf * 16 + h2 * 8 + rr], s);
        }
    __syncthreads();
    if (tid < 128) g_invD[z * Cc + c20 + tid] = 1.0f / sD[tid];
}

// ---------------------------------------------------------------------------
// Kernel 3: fused scores+softmax+out.  Per (w = z*8+hp, u1-tile of 128):
//   loop c2-tiles: S = Q_rows.K^T (Q frags in regs), e = exp(S/8)*invD[c2]
//   (fp16, fed directly as A-frags), O += e @ V[b,hp]
// ---------------------------------------------------------------------------
__global__ __launch_bounds__(256) void k_fused(float* __restrict__ out) {
    __half* Ks = dsm;                             // [128 c2][STH]
    __half* Vs = dsm + TILEH;                     // [128 d][VSTH]
    float* iDs = (float*)(dsm + TILEH + 128 * VSTH);
    const int tid = threadIdx.x, lane = tid & 31, wid = tid >> 5;
    const int tg = lane & 3, rr = lane >> 2;
    const int u1t = blockIdx.x;
    const int w = blockIdx.y;
    const int b = w >> 6, h = (w >> 3) & 7, hp = w & 7, z = w >> 3;
    const float* Qh = g_Pq + (size_t)z * Cc * Kk;
    const float* Kh = g_Pk + (size_t)z * Cc * Kk;
    const float* Bv = g_Pv + (size_t)b * Cc * HV + (size_t)hp * Uu * HV;
    const float* iD = g_invD + z * Cc;

    // Q fragments in registers: warp rows u1 = u1t*128 + wid*16 + {rr, rr+8}
    const int u1r = u1t * 128 + wid * 16 + rr;
    const float* Q0 = Qh + (size_t)(8 * u1r + hp) * Kk;
    const float* Q1 = Q0 + (size_t)64 * Kk;       // u1+8 -> q+64
    uint32_t Qa[4][4];
#pragma unroll
    for (int ks = 0; ks < 4; ks++) {
        float2 v00 = *(const float2*)(Q0 + ks * 16 + 2 * tg);
        float2 v10 = *(const float2*)(Q1 + ks * 16 + 2 * tg);
        float2 v01 = *(const float2*)(Q0 + ks * 16 + 8 + 2 * tg);
        float2 v11 = *(const float2*)(Q1 + ks * 16 + 8 + 2 * tg);
        Qa[ks][0] = pack2(v00.x, v00.y);
        Qa[ks][1] = pack2(v10.x, v10.y);
        Qa[ks][2] = pack2(v01.x, v01.y);
        Qa[ks][3] = pack2(v11.x, v11.y);
    }

    float of[16][4];
#pragma unroll
    for (int i = 0; i < 16; i++)
#pragma unroll
        for (int c = 0; c < 4; c++) of[i][c] = 0.f;

    const uint32_t ksb = s2u(Ks), vsb = s2u(Vs);
    const int brow = (lane & 7) + ((lane >> 4) << 3);
    const int kB = ((lane >> 3) & 1) << 3;

    for (int c2t = 0; c2t < Cc / 128; c2t++) {
        const int c20 = c2t * 128;
        if (c2t) __syncthreads();
        // fill K tile [128 c2][64 k]
        fillA32_once(Kh + (size_t)c20 * Kk, Kk, Ks, tid);
        // fill V tile transposed: Vs[d][c2_local]
        {
            const int d = tid & 127, k8 = (tid >> 7) * 8;
#pragma unroll
            for (int p = 0; p < 8; p++) {
                int kb = k8 + p * 16;
                const float* src = Bv + (size_t)(c20 + kb) * Vd + d;
                float f[8];
#pragma unroll
                for (int j = 0; j < 8; j++) f[j] = src[(size_t)j * Vd];
                *(uint4*)(Vs + d * VSTH + kb) =
                    make_uint4(pack2(f[0], f[1]), pack2(f[2], f[3]),
                               pack2(f[4], f[5]), pack2(f[6], f[7]));
            }
        }
        if (tid < 128) iDs[tid] = iD[c20 + tid];
        __syncthreads();

        // GEMM1: S[16 u1][128 c2]
        float cf[16][4];
#pragma unroll
        for (int i = 0; i < 16; i++)
#pragma unroll
            for (int c = 0; c < 4; c++) cf[i][c] = 0.f;
#pragma unroll
        for (int ks = 0; ks < 4; ks++) {
#pragma unroll
            for (int j = 0; j < 8; j++) {
                uint32_t bfr[4];
                ldm4(bfr, ksb + (uint32_t)(((j * 16 + brow) * STH + ks * 16 + kB) * 2));
                mma16(cf[2 * j], Qa[ks], bfr);
                mma16(cf[2 * j + 1], Qa[ks], bfr + 2);
            }
        }

        // exp * invD -> fp16 A-fragments for GEMM2
        uint32_t ak[8][4];
#pragma unroll
        for (int nf = 0; nf < 16; nf++) {
            float2 idv = *(const float2*)(iDs + nf * 8 + 2 * tg);
            float e0 = __expf(cf[nf][0] * 0.125f) * idv.x;
            float e1 = __expf(cf[nf][1] * 0.125f) * idv.y;
            float e2 = __expf(cf[nf][2] * 0.125f) * idv.x;
            float e3 = __expf(cf[nf][3] * 0.125f) * idv.y;
            ak[nf >> 1][(nf & 1) * 2 + 0] = pack2(e0, e1);
            ak[nf >> 1][(nf & 1) * 2 + 1] = pack2(e2, e3);
        }

        // GEMM2: O[16 u1][128 d] += e @ V
#pragma unroll
        for (int kb = 0; kb < 8; kb++) {
#pragma unroll
            for (int j = 0; j < 8; j++) {
                uint32_t bfr[4];
                ldm4(bfr, vsb + (uint32_t)(((j * 16 + brow) * VSTH + kb * 16 + kB) * 2));
                mma16(of[2 * j], ak[kb], bfr);
                mma16(of[2 * j + 1], ak[kb], bfr + 2);
            }
        }
    }

    // epilogue: rows c1 = h*256 + u1, cols hp*128 + d
    float* g0 = out + ((size_t)b * Cc + h * Uu + u1r) * HV + hp * Vd;
    float* g1 = g0 + (size_t)8 * HV;
#pragma unroll
    for (int df = 0; df < 16; df++) {
        int d = df * 8 + 2 * tg;
        *(float2*)(g0 + d) = make_float2(of[df][0], of[df][1]);
        *(float2*)(g1 + d) = make_float2(of[df][2], of[df][3]);
    }
}

// ---------------------------------------------------------------------------
extern "C" void kernel_launch(void* const* d_in, const int* in_sizes, int n_in,
                              void* d_out, int out_size) {
    (void)in_sizes; (void)n_in; (void)out_size;
    const float* x  = (const float*)d_in[0];
    const float* Mq = (const float*)d_in[1];
    const float* Mk = (const float*)d_in[2];
    const float* Mv = (const float*)d_in[3];
    float* out = (float*)d_out;

    float *pPq, *pPk, *pPv;
    cudaGetSymbolAddress((void**)&pPq, g_Pq);
    cudaGetSymbolAddress((void**)&pPk, g_Pk);
    cudaGetSymbolAddress((void**)&pPv, g_Pv);

    const int DSMP = 4 * TILEH * sizeof(__half);                    // 73728
    const int DSMF = (TILEH + 128 * VSTH) * sizeof(__half) + 512;   // 53760
    static bool attr_done = false;
    if (!attr_done) {
        cudaFuncSetAttribute(k_proj, cudaFuncAttributeMaxDynamicSharedMemorySize, DSMP);
        cudaFuncSetAttribute(k_fused, cudaFuncAttributeMaxDynamicSharedMemorySize, DSMF);
        attr_done = true;
    }

    k_proj<<<dim3(HK / 128, (Bb * Cc) / 128), 256, DSMP>>>(x, Mq, pPq, HK);
    k_proj<<<dim3(HK / 128, (Bb * Cc) / 128), 256, DSMP>>>(x, Mk, pPk, HK);
    k_proj<<<dim3(HV / 128, (Bb * Cc) / 128), 256, DSMP>>>(x, Mv, pPv, HV);
    k_sums<<<dim3(Cc / 128, Bb * 8), 256>>>();
    k_fused<<<dim3(Uu / 128, Bb * 8 * 8), 256, DSMF>>>(out);
}

// round 7
// speedup vs baseline: 3.5523x; 1.0837x over previous
#include <cuda_runtime.h>
#include <cuda_fp16.h>
#include <cstdint>

#define Bb 4
#define Cc 2048
#define Dd 1024
#define Kk 64
#define HK 512
#define HV 1024
#define Vd 128
#define Uu 256

#define KT 64
#define STH 72                  // smem stride (halves), K/Q tiles
#define TILEH (128 * STH)
#define VSTH 136                // smem stride (halves), V tile [c2][d]
#define VTILEH (128 * VSTH)

// ---------------------------------------------------------------------------
// Scratch — projections stored fp16 (every consumer rounds to half anyway)
// ---------------------------------------------------------------------------
__device__ __align__(16) __half g_Pq[(size_t)Bb * Cc * HK];
__device__ __align__(16) __half g_Pk[(size_t)Bb * Cc * HK];
__device__ __align__(16) __half g_Pv[(size_t)Bb * Cc * HV];
__device__ __align__(16) float g_invD[Bb * 8 * Cc];

// ---------------------------------------------------------------------------
__device__ __forceinline__ uint32_t pack2(float x, float y) {
    __half2 h = __floats2half2_rn(x, y);
    return *reinterpret_cast<uint32_t*>(&h);
}

__device__ __forceinline__ void mma16(float* c, const uint32_t* a, const uint32_t* b) {
    asm volatile(
        "mma.sync.aligned.m16n8k16.row.col.f32.f16.f16.f32 "
        "{%0,%1,%2,%3}, {%4,%5,%6,%7}, {%8,%9}, {%0,%1,%2,%3};"
        : "+f"(c[0]), "+f"(c[1]), "+f"(c[2]), "+f"(c[3])
        : "r"(a[0]), "r"(a[1]), "r"(a[2]), "r"(a[3]), "r"(b[0]), "r"(b[1]));
}

__device__ __forceinline__ void ldm4(uint32_t* r, uint32_t addr) {
    asm volatile(
        "ldmatrix.sync.aligned.m8n8.x4.shared.b16 {%0,%1,%2,%3}, [%4];"
        : "=r"(r[0]), "=r"(r[1]), "=r"(r[2]), "=r"(r[3]) : "r"(addr));
}

__device__ __forceinline__ void ldm4t(uint32_t* r, uint32_t addr) {
    asm volatile(
        "ldmatrix.sync.aligned.m8n8.x4.trans.shared.b16 {%0,%1,%2,%3}, [%4];"
        : "=r"(r[0]), "=r"(r[1]), "=r"(r[2]), "=r"(r[3]) : "r"(addr));
}

__device__ __forceinline__ uint32_t s2u(const void* p) {
    return (uint32_t)__cvta_generic_to_shared(p);
}

__device__ __forceinline__ void cpa16(uint32_t d, const void* s) {
    asm volatile("cp.async.cg.shared.global [%0], [%1], 16;" :: "r"(d), "l"(s));
}
__device__ __forceinline__ void cp_commit() {
    asm volatile("cp.async.commit_group;");
}
template <int N> __device__ __forceinline__ void cp_wait() {
    asm volatile("cp.async.wait_group %0;" :: "n"(N));
}

// 64-deep k-tile warp mma via ldmatrix: warp tile 32(m) x 64(n).
template <int SB>
__device__ __forceinline__ void warp_mma64(const __half* As, const __half* Bs,
                                           float acc[2][8][4],
                                           int wy, int wx, int lane) {
    const uint32_t ab = s2u(As), bb = s2u(Bs);
    const int arow = wy * 32 + (lane & 15);
    const int kA = (lane >> 4) << 3;
    const int brow = wx * 64 + (lane & 7) + ((lane >> 4) << 3);
    const int kB = ((lane >> 3) & 1) << 3;
#pragma unroll
    for (int ks = 0; ks < 4; ks++) {
        uint32_t a[2][4];
        ldm4(a[0], ab + (uint32_t)((arow * STH + ks * 16 + kA) * 2));
        ldm4(a[1], ab + (uint32_t)(((arow + 16) * STH + ks * 16 + kA) * 2));
#pragma unroll
        for (int j = 0; j < 4; j++) {
            uint32_t b[4];
            ldm4(b, bb + (uint32_t)(((brow + j * 16) * SB + ks * 16 + kB) * 2));
            mma16(acc[0][2 * j], a[0], b);
            mma16(acc[0][2 * j + 1], a[0], b + 2);
            mma16(acc[1][2 * j], a[1], b);
            mma16(acc[1][2 * j + 1], a[1], b + 2);
        }
    }
}

// ---------------------------------------------------------------------------
// k_proj fills (fp32 sources, convert to half, register-staged ping-pong)
// ---------------------------------------------------------------------------
struct StA { uint2 v[8]; };
__device__ __forceinline__ void stageA32(const float* __restrict__ g, int ld,
                                         int tid, StA& s) {
    const int kq = (tid & 15) * 4, r0 = tid >> 4;
#pragma unroll
    for (int p = 0; p < 8; p++) {
        int r = r0 + p * 16;
        float4 v = *(const float4*)(g + (size_t)r * ld + kq);
        s.v[p] = make_uint2(pack2(v.x, v.y), pack2(v.z, v.w));
    }
}
__device__ __forceinline__ void commitA(const StA& s, __half* As, int tid) {
    const int kq = (tid & 15) * 4, r0 = tid >> 4;
#pragma unroll
    for (int p = 0; p < 8; p++)
        *(uint2*)(As + (r0 + p * 16) * STH + kq) = s.v[p];
}

struct StB { uint4 v[4]; };
__device__ __forceinline__ void stageBT(const float* __restrict__ g, int ld,
                                        int tid, StB& s) {
    const int n = tid & 127, k8 = (tid >> 7) * 8;
#pragma unroll
    for (int p = 0; p < 4; p++) {
        int kb = k8 + p * 16;
        float f[8];
#pragma unroll
        for (int j = 0; j < 8; j++) f[j] = g[(size_t)(kb + j) * ld + n];
        s.v[p] = make_uint4(pack2(f[0], f[1]), pack2(f[2], f[3]),
                            pack2(f[4], f[5]), pack2(f[6], f[7]));
    }
}
__device__ __forceinline__ void commitB(const StB& s, __half* Bs, int tid) {
    const int n = tid & 127, k8 = (tid >> 7) * 8;
#pragma unroll
    for (int p = 0; p < 4; p++)
        *(uint4*)(Bs + n * STH + k8 + p * 16) = s.v[p];
}

// ---------------------------------------------------------------------------
// Kernel 1: projection  P[8192,N](half) = X[8192,1024] @ W[1024,N]
// ---------------------------------------------------------------------------
extern __shared__ __align__(16) __half dsm[];

__global__ __launch_bounds__(256) void k_proj(const float* __restrict__ X,
                                              const float* __restrict__ W,
                                              __half* __restrict__ P, int N) {
    __half* Abuf[2] = {dsm, dsm + 2 * TILEH};
    __half* Bbuf[2] = {dsm + TILEH, dsm + 3 * TILEH};
    const int tid = threadIdx.x, lane = tid & 31, wid = tid >> 5;
    const int wy = wid & 3, wx = wid >> 2;
    const int m0 = blockIdx.y * 128, n0 = blockIdx.x * 128;

    float acc[2][8][4];
#pragma unroll
    for (int i = 0; i < 2; i++)
#pragma unroll
        for (int j = 0; j < 8; j++)
#pragma unroll
            for (int c = 0; c < 4; c++) acc[i][j][c] = 0.f;

    StA sa; StB sb;
    stageA32(X + (size_t)m0 * Dd, Dd, tid, sa);
    stageBT(W + n0, N, tid, sb);
    commitA(sa, Abuf[0], tid);
    commitB(sb, Bbuf[0], tid);
    __syncthreads();

    const int NIT = Dd / KT;
    for (int it = 0; it < NIT; it++) {
        bool more = (it + 1) < NIT;
        if (more) {
            int k0n = (it + 1) * KT;
            stageA32(X + (size_t)m0 * Dd + k0n, Dd, tid, sa);
            stageBT(W + (size_t)k0n * N + n0, N, tid, sb);
        }
        warp_mma64<STH>(Abuf[it & 1], Bbuf[it & 1], acc, wy, wx, lane);
        if (more) {
            commitA(sa, Abuf[(it + 1) & 1], tid);
            commitB(sb, Bbuf[(it + 1) & 1], tid);
        }
        __syncthreads();
    }

    const int tg = lane & 3, rr = lane >> 2;
#pragma unroll
    for (int mf = 0; mf < 2; mf++) {
        int m = m0 + wy * 32 + mf * 16 + rr;
#pragma unroll
        for (int nf = 0; nf < 8; nf++) {
            int n = n0 + wx * 64 + nf * 8 + tg * 2;
            *(uint32_t*)(P + (size_t)m * N + n) =
                pack2(acc[mf][nf][0], acc[mf][nf][1]);
            *(uint32_t*)(P + (size_t)(m + 8) * N + n) =
                pack2(acc[mf][nf][2], acc[mf][nf][3]);
        }
    }
}

// ---------------------------------------------------------------------------
// Kernel 2: invD[z][c2] = 1/sum_q exp(S/8).  K tile resident; Q tiles
// cp.async double-buffered.
// ---------------------------------------------------------------------------
__global__ __launch_bounds__(256) void k_sums() {
    __half* As = dsm;
    __half* Bs[2] = {dsm + TILEH, dsm + 2 * TILEH};
    float* sD = (float*)(dsm + 3 * TILEH);
    const int tid = threadIdx.x, lane = tid & 31, wid = tid >> 5;
    const int wy = wid & 3, wx = wid >> 2;
    const int tg = lane & 3, rr = lane >> 2;
    const int z = blockIdx.y;
    const int c20 = blockIdx.x * 128;
    const __half* Kh = g_Pk + (size_t)z * Cc * Kk;
    const __half* Qh = g_Pq + (size_t)z * Cc * Kk;

    if (tid < 128) sD[tid] = 0.f;

    // prologue group: K tile + Q tile 0
#pragma unroll
    for (int p = 0; p < 4; p++) {
        int id = tid + 256 * p, r = id >> 3, c = id & 7;
        cpa16(s2u(As + r * STH + c * 8), Kh + (size_t)(c20 + r) * Kk + c * 8);
        cpa16(s2u(Bs[0] + r * STH + c * 8), Qh + (size_t)r * Kk + c * 8);
    }
    cp_commit();

    float rs[2][2] = {{0.f, 0.f}, {0.f, 0.f}};
    const int NT = Cc / 128;
    for (int t = 0; t < NT; t++) {
        __syncthreads();
        if (t + 1 < NT) {
            const __half* src = Qh + (size_t)(t + 1) * 128 * Kk;
            __half* dst = Bs[(t + 1) & 1];
#pragma unroll
            for (int p = 0; p < 4; p++) {
                int id = tid + 256 * p, r = id >> 3, c = id & 7;
                cpa16(s2u(dst + r * STH + c * 8), src + (size_t)r * Kk + c * 8);
            }
            cp_commit();
            cp_wait<1>();
        } else {
            cp_wait<0>();
        }
        __syncthreads();

        float acc[2][8][4];
#pragma unroll
        for (int i = 0; i < 2; i++)
#pragma unroll
            for (int j = 0; j < 8; j++)
#pragma unroll
                for (int c = 0; c < 4; c++) acc[i][j][c] = 0.f;
        warp_mma64<STH>(As, Bs[t & 1], acc, wy, wx, lane);
#pragma unroll
        for (int mf = 0; mf < 2; mf++)
#pragma unroll
            for (int nf = 0; nf < 8; nf++) {
                rs[mf][0] += __expf(acc[mf][nf][0] * 0.125f)
                           + __expf(acc[mf][nf][1] * 0.125f);
                rs[mf][1] += __expf(acc[mf][nf][2] * 0.125f)
                           + __expf(acc[mf][nf][3] * 0.125f);
            }
    }
#pragma unroll
    for (int mf = 0; mf < 2; mf++)
#pragma unroll
        for (int h2 = 0; h2 < 2; h2++) {
            float s = rs[mf][h2];
            s += __shfl_xor_sync(0xffffffffu, s, 1);
            s += __shfl_xor_sync(0xffffffffu, s, 2);
            if (tg == 0)
                atomicAdd(&sD[wy * 32 + mf * 16 + h2 * 8 + rr], s);
        }
    __syncthreads();
    if (tid < 128) g_invD[z * Cc + c20 + tid] = 1.0f / sD[tid];
}

// ---------------------------------------------------------------------------
// Kernel 3: fused scores+softmax+PV.  cp.async double-buffered K/V/iD tiles,
// V stored natural [c2][d] + ldmatrix.trans for GEMM2 B-frags.
// ---------------------------------------------------------------------------
__global__ __launch_bounds__(256) void k_fused(float* __restrict__ out) {
    __half* Ks[2] = {dsm, dsm + TILEH};
    __half* Vs[2] = {dsm + 2 * TILEH, dsm + 2 * TILEH + VTILEH};
    float* iDs[2] = {(float*)(dsm + 2 * TILEH + 2 * VTILEH),
                     (float*)(dsm + 2 * TILEH + 2 * VTILEH) + 128};
    const int tid = threadIdx.x, lane = tid & 31, wid = tid >> 5;
    const int tg = lane & 3, rr = lane >> 2;
    const int u1t = blockIdx.x;
    const int w = blockIdx.y;
    const int b = w >> 6, h = (w >> 3) & 7, hp = w & 7, z = w >> 3;
    const __half* Qh = g_Pq + (size_t)z * Cc * Kk;
    const __half* Kh = g_Pk + (size_t)z * Cc * Kk;
    const __half* Bv = g_Pv + (size_t)b * Cc * HV + (size_t)hp * Uu * HV;
    const float* iD = g_invD + z * Cc;

    // Q fragments (half source, direct uint32 loads)
    const int u1r = u1t * 128 + wid * 16 + rr;
    const __half* Q0 = Qh + (size_t)(8 * u1r + hp) * Kk;
    const __half* Q1 = Q0 + (size_t)64 * Kk;
    uint32_t Qa[4][4];
#pragma unroll
    for (int ks = 0; ks < 4; ks++) {
        Qa[ks][0] = *(const uint32_t*)(Q0 + ks * 16 + 2 * tg);
        Qa[ks][1] = *(const uint32_t*)(Q1 + ks * 16 + 2 * tg);
        Qa[ks][2] = *(const uint32_t*)(Q0 + ks * 16 + 8 + 2 * tg);
        Qa[ks][3] = *(const uint32_t*)(Q1 + ks * 16 + 8 + 2 * tg);
    }

    float of[16][4];
#pragma unroll
    for (int i = 0; i < 16; i++)
#pragma unroll
        for (int c = 0; c < 4; c++) of[i][c] = 0.f;

    // tile fill (pure half copies via cp.async)
    auto fill = [&](int c20, __half* ks, __half* vs, float* ids) {
#pragma unroll
        for (int p = 0; p < 4; p++) {
            int id = tid + 256 * p, r = id >> 3, c = id & 7;
            cpa16(s2u(ks + r * STH + c * 8), Kh + (size_t)(c20 + r) * Kk + c * 8);
        }
#pragma unroll
        for (int p = 0; p < 8; p++) {
            int id = tid + 256 * p, r = id >> 4, c = id & 15;
            cpa16(s2u(vs + r * VSTH + c * 8), Bv + (size_t)(c20 + r) * Vd + c * 8);
        }
        if (tid < 32) cpa16(s2u(ids + tid * 4), iD + c20 + tid * 4);
    };

    fill(0, Ks[0], Vs[0], iDs[0]);
    cp_commit();

    const int brow = (lane & 7) + ((lane >> 4) << 3);
    const int kB = ((lane >> 3) & 1) << 3;
    const int vkrow = (lane & 7) + (((lane >> 3) & 1) << 3);  // trans k-row
    const int vcol = (lane >> 4) << 3;                        // trans n-col

    const int NT = Cc / 128;
    for (int t = 0; t < NT; t++) {
        __syncthreads();
        if (t + 1 < NT) {
            fill((t + 1) * 128, Ks[(t + 1) & 1], Vs[(t + 1) & 1], iDs[(t + 1) & 1]);
            cp_commit();
            cp_wait<1>();
        } else {
            cp_wait<0>();
        }
        __syncthreads();

        const uint32_t ksb = s2u(Ks[t & 1]), vsb = s2u(Vs[t & 1]);
        const float* ids = iDs[t & 1];

        // GEMM1: S[16 u1][128 c2]
        float cf[16][4];
#pragma unroll
        for (int i = 0; i < 16; i++)
#pragma unroll
            for (int c = 0; c < 4; c++) cf[i][c] = 0.f;
#pragma unroll
        for (int ks = 0; ks < 4; ks++) {
#pragma unroll
            for (int j = 0; j < 8; j++) {
                uint32_t bfr[4];
                ldm4(bfr, ksb + (uint32_t)(((j * 16 + brow) * STH + ks * 16 + kB) * 2));
                mma16(cf[2 * j], Qa[ks], bfr);
                mma16(cf[2 * j + 1], Qa[ks], bfr + 2);
            }
        }

        // exp * invD -> fp16 A-frags
        uint32_t ak[8][4];
#pragma unroll
        for (int nf = 0; nf < 16; nf++) {
            float2 idv = *(const float2*)(ids + nf * 8 + 2 * tg);
            float e0 = __expf(cf[nf][0] * 0.125f) * idv.x;
            float e1 = __expf(cf[nf][1] * 0.125f) * idv.y;
            float e2 = __expf(cf[nf][2] * 0.125f) * idv.x;
            float e3 = __expf(cf[nf][3] * 0.125f) * idv.y;
            ak[nf >> 1][(nf & 1) * 2 + 0] = pack2(e0, e1);
            ak[nf >> 1][(nf & 1) * 2 + 1] = pack2(e2, e3);
        }

        // GEMM2: O += e @ V, B-frags via ldmatrix.trans on [c2][d] tile
#pragma unroll
        for (int kb = 0; kb < 8; kb++) {
#pragma unroll
            for (int j = 0; j < 8; j++) {
                uint32_t bfr[4];
                ldm4t(bfr, vsb + (uint32_t)(((kb * 16 + vkrow) * VSTH + j * 16 + vcol) * 2));
                mma16(of[2 * j], ak[kb], bfr);
                mma16(of[2 * j + 1], ak[kb], bfr + 2);
            }
        }
    }

    float* g0 = out + ((size_t)b * Cc + h * Uu + u1r) * HV + hp * Vd;
    float* g1 = g0 + (size_t)8 * HV;
#pragma unroll
    for (int df = 0; df < 16; df++) {
        int d = df * 8 + 2 * tg;
        *(float2*)(g0 + d) = make_float2(of[df][0], of[df][1]);
        *(float2*)(g1 + d) = make_float2(of[df][2], of[df][3]);
    }
}

// ---------------------------------------------------------------------------
extern "C" void kernel_launch(void* const* d_in, const int* in_sizes, int n_in,
                              void* d_out, int out_size) {
    (void)in_sizes; (void)n_in; (void)out_size;
    const float* x  = (const float*)d_in[0];
    const float* Mq = (const float*)d_in[1];
    const float* Mk = (const float*)d_in[2];
    const float* Mv = (const float*)d_in[3];
    float* out = (float*)d_out;

    __half *pPq, *pPk, *pPv;
    cudaGetSymbolAddress((void**)&pPq, g_Pq);
    cudaGetSymbolAddress((void**)&pPk, g_Pk);
    cudaGetSymbolAddress((void**)&pPv, g_Pv);

    const int DSMP = 4 * TILEH * sizeof(__half);                         // 73728
    const int DSMS = 3 * TILEH * sizeof(__half) + 512;                   // 55808
    const int DSMF = (2 * TILEH + 2 * VTILEH) * sizeof(__half) + 1024;   // 107520
    static bool attr_done = false;
    if (!attr_done) {
        cudaFuncSetAttribute(k_proj, cudaFuncAttributeMaxDynamicSharedMemorySize, DSMP);
        cudaFuncSetAttribute(k_sums, cudaFuncAttributeMaxDynamicSharedMemorySize, DSMS);
        cudaFuncSetAttribute(k_fused, cudaFuncAttributeMaxDynamicSharedMemorySize, DSMF);
        attr_done = true;
    }

    k_proj<<<dim3(HK / 128, (Bb * Cc) / 128), 256, DSMP>>>(x, Mq, pPq, HK);
    k_proj<<<dim3(HK / 128, (Bb * Cc) / 128), 256, DSMP>>>(x, Mk, pPk, HK);
    k_proj<<<dim3(HV / 128, (Bb * Cc) / 128), 256, DSMP>>>(x, Mv, pPv, HV);
    k_sums<<<dim3(Cc / 128, Bb * 8), 256, DSMS>>>();
    k_fused<<<dim3(Uu / 128, Bb * 8 * 8), 256, DSMF>>>(out);
}

// round 11
// speedup vs baseline: 5.1327x; 1.4449x over previous
#include <cuda_runtime.h>
#include <cuda_fp16.h>
#include <cstdint>

#define Bb 4
#define Cc 2048
#define Dd 1024
#define Kk 64
#define HK 512
#define HV 1024
#define Vd 128
#define Uu 256

#define STH 72                  // smem stride (halves), [m][k] tiles
#define TILEH (128 * STH)
#define VSTH 136                // smem stride (halves), [k][n] tiles
#define VTILEH (128 * VSTH)
#define BTILEH (64 * VSTH)      // 64-row [k][n] tile for k_projh

// ---------------------------------------------------------------------------
// Scratch — natural layouts (R7-validated consumer addressing)
// ---------------------------------------------------------------------------
__device__ __align__(16) __half g_Xh[(size_t)Bb * Cc * Dd];       // 16 MB
__device__ __align__(16) __half g_Wq[(size_t)Dd * HK];
__device__ __align__(16) __half g_Wk[(size_t)Dd * HK];
__device__ __align__(16) __half g_Wv[(size_t)Dd * HV];
__device__ __align__(16) __half g_Pq[(size_t)Bb * Cc * HK];
__device__ __align__(16) __half g_Pk[(size_t)Bb * Cc * HK];
__device__ __align__(16) __half g_Pv[(size_t)Bb * Cc * HV];
__device__ __align__(16) float g_invD[Bb * 8 * Cc];

// ---------------------------------------------------------------------------
__device__ __forceinline__ uint32_t pack2(float x, float y) {
    __half2 h = __floats2half2_rn(x, y);
    return *reinterpret_cast<uint32_t*>(&h);
}

__device__ __forceinline__ void mma16(float* c, const uint32_t* a, const uint32_t* b) {
    asm volatile(
        "mma.sync.aligned.m16n8k16.row.col.f32.f16.f16.f32 "
        "{%0,%1,%2,%3}, {%4,%5,%6,%7}, {%8,%9}, {%0,%1,%2,%3};"
        : "+f"(c[0]), "+f"(c[1]), "+f"(c[2]), "+f"(c[3])
        : "r"(a[0]), "r"(a[1]), "r"(a[2]), "r"(a[3]), "r"(b[0]), "r"(b[1]));
}

__device__ __forceinline__ void ldm4(uint32_t* r, uint32_t addr) {
    asm volatile(
        "ldmatrix.sync.aligned.m8n8.x4.shared.b16 {%0,%1,%2,%3}, [%4];"
        : "=r"(r[0]), "=r"(r[1]), "=r"(r[2]), "=r"(r[3]) : "r"(addr));
}

__device__ __forceinline__ void ldm4t(uint32_t* r, uint32_t addr) {
    asm volatile(
        "ldmatrix.sync.aligned.m8n8.x4.trans.shared.b16 {%0,%1,%2,%3}, [%4];"
        : "=r"(r[0]), "=r"(r[1]), "=r"(r[2]), "=r"(r[3]) : "r"(addr));
}

__device__ __forceinline__ uint32_t s2u(const void* p) {
    return (uint32_t)__cvta_generic_to_shared(p);
}

__device__ __forceinline__ void cpa16(uint32_t d, const void* s) {
    asm volatile("cp.async.cg.shared.global [%0], [%1], 16;" :: "r"(d), "l"(s));
}
__device__ __forceinline__ void cp_commit() {
    asm volatile("cp.async.commit_group;");
}
template <int N> __device__ __forceinline__ void cp_wait() {
    asm volatile("cp.async.wait_group %0;" :: "n"(N));
}

// 64-deep k-tile warp mma, A [m][STH] via ldm4, B [n][SB] via ldm4.  (R7)
template <int SB>
__device__ __forceinline__ void warp_mma64(const __half* As, const __half* Bs,
                                           float acc[2][8][4],
                                           int wy, int wx, int lane) {
    const uint32_t ab = s2u(As), bb = s2u(Bs);
    const int arow = wy * 32 + (lane & 15);
    const int kA = (lane >> 4) << 3;
    const int brow = wx * 64 + (lane & 7) + ((lane >> 4) << 3);
    const int kB = ((lane >> 3) & 1) << 3;
#pragma unroll
    for (int ks = 0; ks < 4; ks++) {
        uint32_t a[2][4];
        ldm4(a[0], ab + (uint32_t)((arow * STH + ks * 16 + kA) * 2));
        ldm4(a[1], ab + (uint32_t)(((arow + 16) * STH + ks * 16 + kA) * 2));
#pragma unroll
        for (int j = 0; j < 4; j++) {
            uint32_t b[4];
            ldm4(b, bb + (uint32_t)(((brow + j * 16) * SB + ks * 16 + kB) * 2));
            mma16(acc[0][2 * j], a[0], b);
            mma16(acc[0][2 * j + 1], a[0], b + 2);
            mma16(acc[1][2 * j], a[1], b);
            mma16(acc[1][2 * j + 1], a[1], b + 2);
        }
    }
}

// 64-deep k-tile warp mma, A [m][STH] via ldm4, B natural [k][SB] via ldm4t.
template <int SB>
__device__ __forceinline__ void warp_mma64t(const __half* As, const __half* Bs,
                                            float acc[2][8][4],
                                            int wy, int wx, int lane) {
    const uint32_t ab = s2u(As), bb = s2u(Bs);
    const int arow = wy * 32 + (lane & 15);
    const int kA = (lane >> 4) << 3;
    const int vkrow = (lane & 7) + (((lane >> 3) & 1) << 3);
    const int vcol = (lane >> 4) << 3;
#pragma unroll
    for (int ks = 0; ks < 4; ks++) {
        uint32_t a[2][4];
        ldm4(a[0], ab + (uint32_t)((arow * STH + ks * 16 + kA) * 2));
        ldm4(a[1], ab + (uint32_t)(((arow + 16) * STH + ks * 16 + kA) * 2));
#pragma unroll
        for (int j = 0; j < 4; j++) {
            uint32_t b[4];
            ldm4t(b, bb + (uint32_t)(((ks * 16 + vkrow) * SB + wx * 64 + j * 16 + vcol) * 2));
            mma16(acc[0][2 * j], a[0], b);
            mma16(acc[0][2 * j + 1], a[0], b + 2);
            mma16(acc[1][2 * j], a[1], b);
            mma16(acc[1][2 * j + 1], a[1], b + 2);
        }
    }
}

// ---------------------------------------------------------------------------
// Convert kernel: fp32 -> fp16, 2048 elems per block
// ---------------------------------------------------------------------------
__global__ void k_cvt(const float* __restrict__ src, __half* __restrict__ dst) {
    size_t i = ((size_t)blockIdx.x * 256 + threadIdx.x) * 8;
    float4 a = *(const float4*)(src + i);
    float4 b = *(const float4*)(src + i + 4);
    *(uint4*)(dst + i) = make_uint4(pack2(a.x, a.y), pack2(a.z, a.w),
                                    pack2(b.x, b.y), pack2(b.z, b.w));
}

// ---------------------------------------------------------------------------
// Kernel: half GEMM  P[8192,N] = Xh[8192,1024] @ Wh[1024,N]  (all half)
// cp.async double-buffered; A ldm4, B ldm4t on natural [k][n].
// ---------------------------------------------------------------------------
extern __shared__ __align__(16) __half dsm[];

__global__ __launch_bounds__(256) void k_projh(const __half* __restrict__ X,
                                               const __half* __restrict__ W,
                                               __half* __restrict__ P, int N) {
    __half* Apb[2] = {dsm, dsm + TILEH};
    __half* Bpb[2] = {dsm + 2 * TILEH, dsm + 2 * TILEH + BTILEH};
    const int tid = threadIdx.x, lane = tid & 31, wid = tid >> 5;
    const int wy = wid & 3, wx = wid >> 2;
    const int m0 = blockIdx.y * 128, n0 = blockIdx.x * 128;

    float acc[2][8][4];
#pragma unroll
    for (int i = 0; i < 2; i++)
#pragma unroll
        for (int j = 0; j < 8; j++)
#pragma unroll
            for (int c = 0; c < 4; c++) acc[i][j][c] = 0.f;

    auto fill = [&](int k0, __half* a, __half* bs) {
#pragma unroll
        for (int p = 0; p < 4; p++) {           // A: 128 rows x 64 k
            int id = tid + 256 * p, r = id >> 3, c = id & 7;
            cpa16(s2u(a + r * STH + c * 8), X + (size_t)(m0 + r) * Dd + k0 + c * 8);
        }
#pragma unroll
        for (int p = 0; p < 4; p++) {           // B: 64 k-rows x 128 n
            int id = tid + 256 * p, r = id >> 4, c = id & 15;
            cpa16(s2u(bs + r * VSTH + c * 8), W + (size_t)(k0 + r) * N + n0 + c * 8);
        }
    };

    fill(0, Apb[0], Bpb[0]);
    cp_commit();

    const int NT = Dd / 64;
    for (int t = 0; t < NT; t++) {
        if (t + 1 < NT) {
            fill((t + 1) * 64, Apb[(t + 1) & 1], Bpb[(t + 1) & 1]);
            cp_commit();
            cp_wait<1>();
        } else {
            cp_wait<0>();
        }
        __syncthreads();
        warp_mma64t<VSTH>(Apb[t & 1], Bpb[t & 1], acc, wy, wx, lane);
        __syncthreads();
    }

    const int tg = lane & 3, rr = lane >> 2;
#pragma unroll
    for (int mf = 0; mf < 2; mf++) {
        int m = m0 + wy * 32 + mf * 16 + rr;
#pragma unroll
        for (int nf = 0; nf < 8; nf++) {
            int n = n0 + wx * 64 + nf * 8 + tg * 2;
            *(uint32_t*)(P + (size_t)m * N + n) = pack2(acc[mf][nf][0], acc[mf][nf][1]);
            *(uint32_t*)(P + (size_t)(m + 8) * N + n) = pack2(acc[mf][nf][2], acc[mf][nf][3]);
        }
    }
}

// ---------------------------------------------------------------------------
// Kernel 2 (R7 verbatim): invD[z][c2] = 1/sum_q exp(S/8).
// Flat-chunk head addressing (stride 64) — encodes the raw reshape.
// ---------------------------------------------------------------------------
__global__ __launch_bounds__(256) void k_sums() {
    __half* As = dsm;
    __half* Bs[2] = {dsm + TILEH, dsm + 2 * TILEH};
    float* sD = (float*)(dsm + 3 * TILEH);
    const int tid = threadIdx.x, lane = tid & 31, wid = tid >> 5;
    const int wy = wid & 3, wx = wid >> 2;
    const int tg = lane & 3, rr = lane >> 2;
    const int z = blockIdx.y;
    const int c20 = blockIdx.x * 128;
    const __half* Kh = g_Pk + (size_t)z * Cc * Kk;
    const __half* Qh = g_Pq + (size_t)z * Cc * Kk;

    if (tid < 128) sD[tid] = 0.f;

#pragma unroll
    for (int p = 0; p < 4; p++) {
        int id = tid + 256 * p, r = id >> 3, c = id & 7;
        cpa16(s2u(As + r * STH + c * 8), Kh + (size_t)(c20 + r) * Kk + c * 8);
        cpa16(s2u(Bs[0] + r * STH + c * 8), Qh + (size_t)r * Kk + c * 8);
    }
    cp_commit();

    float rs[2][2] = {{0.f, 0.f}, {0.f, 0.f}};
    const int NT = Cc / 128;
    for (int t = 0; t < NT; t++) {
        __syncthreads();
        if (t + 1 < NT) {
            const __half* src = Qh + (size_t)(t + 1) * 128 * Kk;
            __half* dst = Bs[(t + 1) & 1];
#pragma unroll
            for (int p = 0; p < 4; p++) {
                int id = tid + 256 * p, r = id >> 3, c = id & 7;
                cpa16(s2u(dst + r * STH + c * 8), src + (size_t)r * Kk + c * 8);
            }
            cp_commit();
            cp_wait<1>();
        } else {
            cp_wait<0>();
        }
        __syncthreads();

        float acc[2][8][4];
#pragma unroll
        for (int i = 0; i < 2; i++)
#pragma unroll
            for (int j = 0; j < 8; j++)
#pragma unroll
                for (int c = 0; c < 4; c++) acc[i][j][c] = 0.f;
        warp_mma64<STH>(As, Bs[t & 1], acc, wy, wx, lane);
#pragma unroll
        for (int mf = 0; mf < 2; mf++)
#pragma unroll
            for (int nf = 0; nf < 8; nf++) {
                rs[mf][0] += __expf(acc[mf][nf][0] * 0.125f)
                           + __expf(acc[mf][nf][1] * 0.125f);
                rs[mf][1] += __expf(acc[mf][nf][2] * 0.125f)
                           + __expf(acc[mf][nf][3] * 0.125f);
            }
    }
#pragma unroll
    for (int mf = 0; mf < 2; mf++)
#pragma unroll
        for (int h2 = 0; h2 < 2; h2++) {
            float s = rs[mf][h2];
            s += __shfl_xor_sync(0xffffffffu, s, 1);
            s += __shfl_xor_sync(0xffffffffu, s, 2);
            if (tg == 0)
                atomicAdd(&sD[wy * 32 + mf * 16 + h2 * 8 + rr], s);
        }
    __syncthreads();
    if (tid < 128) g_invD[z * Cc + c20 + tid] = 1.0f / sD[tid];
}

// ---------------------------------------------------------------------------
// Kernel 3 (R7 verbatim): fused scores+softmax+PV.
// ---------------------------------------------------------------------------
__global__ __launch_bounds__(256) void k_fused(float* __restrict__ out) {
    __half* Ks[2] = {dsm, dsm + TILEH};
    __half* Vs[2] = {dsm + 2 * TILEH, dsm + 2 * TILEH + VTILEH};
    float* iDs[2] = {(float*)(dsm + 2 * TILEH + 2 * VTILEH),
                     (float*)(dsm + 2 * TILEH + 2 * VTILEH) + 128};
    const int tid = threadIdx.x, lane = tid & 31, wid = tid >> 5;
    const int tg = lane & 3, rr = lane >> 2;
    const int u1t = blockIdx.x;
    const int w = blockIdx.y;
    const int b = w >> 6, h = (w >> 3) & 7, hp = w & 7, z = w >> 3;
    const __half* Qh = g_Pq + (size_t)z * Cc * Kk;
    const __half* Kh = g_Pk + (size_t)z * Cc * Kk;
    const __half* Bv = g_Pv + (size_t)b * Cc * HV + (size_t)hp * Uu * HV;
    const float* iD = g_invD + z * Cc;

    const int u1r = u1t * 128 + wid * 16 + rr;
    const __half* Q0 = Qh + (size_t)(8 * u1r + hp) * Kk;
    const __half* Q1 = Q0 + (size_t)64 * Kk;
    uint32_t Qa[4][4];
#pragma unroll
    for (int ks = 0; ks < 4; ks++) {
        Qa[ks][0] = *(const uint32_t*)(Q0 + ks * 16 + 2 * tg);
        Qa[ks][1] = *(const uint32_t*)(Q1 + ks * 16 + 2 * tg);
        Qa[ks][2] = *(const uint32_t*)(Q0 + ks * 16 + 8 + 2 * tg);
        Qa[ks][3] = *(const uint32_t*)(Q1 + ks * 16 + 8 + 2 * tg);
    }

    float of[16][4];
#pragma unroll
    for (int i = 0; i < 16; i++)
#pragma unroll
        for (int c = 0; c < 4; c++) of[i][c] = 0.f;

    auto fill = [&](int c20, __half* ks, __half* vs, float* ids) {
#pragma unroll
        for (int p = 0; p < 4; p++) {
            int id = tid + 256 * p, r = id >> 3, c = id & 7;
            cpa16(s2u(ks + r * STH + c * 8), Kh + (size_t)(c20 + r) * Kk + c * 8);
        }
#pragma unroll
        for (int p = 0; p < 8; p++) {
            int id = tid + 256 * p, r = id >> 4, c = id & 15;
            cpa16(s2u(vs + r * VSTH + c * 8), Bv + (size_t)(c20 + r) * Vd + c * 8);
        }
        if (tid < 32) cpa16(s2u(ids + tid * 4), iD + c20 + tid * 4);
    };

    fill(0, Ks[0], Vs[0], iDs[0]);
    cp_commit();

    const int brow = (lane & 7) + ((lane >> 4) << 3);
    const int kB = ((lane >> 3) & 1) << 3;
    const int vkrow = (lane & 7) + (((lane >> 3) & 1) << 3);
    const int vcol = (lane >> 4) << 3;

    const int NT = Cc / 128;
    for (int t = 0; t < NT; t++) {
        __syncthreads();
        if (t + 1 < NT) {
            fill((t + 1) * 128, Ks[(t + 1) & 1], Vs[(t + 1) & 1], iDs[(t + 1) & 1]);
            cp_commit();
            cp_wait<1>();
        } else {
            cp_wait<0>();
        }
        __syncthreads();

        const uint32_t ksb = s2u(Ks[t & 1]), vsb = s2u(Vs[t & 1]);
        const float* ids = iDs[t & 1];

        float cf[16][4];
#pragma unroll
        for (int i = 0; i < 16; i++)
#pragma unroll
            for (int c = 0; c < 4; c++) cf[i][c] = 0.f;
#pragma unroll
        for (int ks = 0; ks < 4; ks++) {
#pragma unroll
            for (int j = 0; j < 8; j++) {
                uint32_t bfr[4];
                ldm4(bfr, ksb + (uint32_t)(((j * 16 + brow) * STH + ks * 16 + kB) * 2));
                mma16(cf[2 * j], Qa[ks], bfr);
                mma16(cf[2 * j + 1], Qa[ks], bfr + 2);
            }
        }

        uint32_t ak[8][4];
#pragma unroll
        for (int nf = 0; nf < 16; nf++) {
            float2 idv = *(const float2*)(ids + nf * 8 + 2 * tg);
            float e0 = __expf(cf[nf][0] * 0.125f) * idv.x;
            float e1 = __expf(cf[nf][1] * 0.125f) * idv.y;
            float e2 = __expf(cf[nf][2] * 0.125f) * idv.x;
            float e3 = __expf(cf[nf][3] * 0.125f) * idv.y;
            ak[nf >> 1][(nf & 1) * 2 + 0] = pack2(e0, e1);
            ak[nf >> 1][(nf & 1) * 2 + 1] = pack2(e2, e3);
        }

#pragma unroll
        for (int kb = 0; kb < 8; kb++) {
#pragma unroll
            for (int j = 0; j < 8; j++) {
                uint32_t bfr[4];
                ldm4t(bfr, vsb + (uint32_t)(((kb * 16 + vkrow) * VSTH + j * 16 + vcol) * 2));
                mma16(of[2 * j], ak[kb], bfr);
                mma16(of[2 * j + 1], ak[kb], bfr + 2);
            }
        }
    }

    float* g0 = out + ((size_t)b * Cc + h * Uu + u1r) * HV + hp * Vd;
    float* g1 = g0 + (size_t)8 * HV;
#pragma unroll
    for (int df = 0; df < 16; df++) {
        int d = df * 8 + 2 * tg;
        *(float2*)(g0 + d) = make_float2(of[df][0], of[df][1]);
        *(float2*)(g1 + d) = make_float2(of[df][2], of[df][3]);
    }
}

// ---------------------------------------------------------------------------
extern "C" void kernel_launch(void* const* d_in, const int* in_sizes, int n_in,
                              void* d_out, int out_size) {
    (void)in_sizes; (void)n_in; (void)out_size;
    const float* x  = (const float*)d_in[0];
    const float* Mq = (const float*)d_in[1];
    const float* Mk = (const float*)d_in[2];
    const float* Mv = (const float*)d_in[3];
    float* out = (float*)d_out;

    __half *pXh, *pWq, *pWk, *pWv, *pPq, *pPk, *pPv;
    cudaGetSymbolAddress((void**)&pXh, g_Xh);
    cudaGetSymbolAddress((void**)&pWq, g_Wq);
    cudaGetSymbolAddress((void**)&pWk, g_Wk);
    cudaGetSymbolAddress((void**)&pWv, g_Wv);
    cudaGetSymbolAddress((void**)&pPq, g_Pq);
    cudaGetSymbolAddress((void**)&pPk, g_Pk);
    cudaGetSymbolAddress((void**)&pPv, g_Pv);

    const int DSMP = (2 * TILEH + 2 * BTILEH) * sizeof(__half);          // 71680
    const int DSMS = 3 * TILEH * sizeof(__half) + 512;                   // 55808
    const int DSMF = (2 * TILEH + 2 * VTILEH) * sizeof(__half) + 1024;   // 107520
    static bool attr_done = false;
    if (!attr_done) {
        cudaFuncSetAttribute(k_projh, cudaFuncAttributeMaxDynamicSharedMemorySize, DSMP);
        cudaFuncSetAttribute(k_sums, cudaFuncAttributeMaxDynamicSharedMemorySize, DSMS);
        cudaFuncSetAttribute(k_fused, cudaFuncAttributeMaxDynamicSharedMemorySize, DSMF);
        attr_done = true;
    }

    // convert pass (all fp32 -> fp16)
    k_cvt<<<(int)(((size_t)Bb * Cc * Dd) / 2048), 256>>>(x, pXh);
    k_cvt<<<(Dd * HK) / 2048, 256>>>(Mq, pWq);
    k_cvt<<<(Dd * HK) / 2048, 256>>>(Mk, pWk);
    k_cvt<<<(int)(((size_t)Dd * HV) / 2048), 256>>>(Mv, pWv);

    // projections (natural layouts; consumers use flat-chunk addressing)
    k_projh<<<dim3(HK / 128, (Bb * Cc) / 128), 256, DSMP>>>(pXh, pWq, pPq, HK);
    k_projh<<<dim3(HK / 128, (Bb * Cc) / 128), 256, DSMP>>>(pXh, pWk, pPk, HK);
    k_projh<<<dim3(HV / 128, (Bb * Cc) / 128), 256, DSMP>>>(pXh, pWv, pPv, HV);

    k_sums<<<dim3(Cc / 128, Bb * 8), 256, DSMS>>>();
    k_fused<<<dim3(Uu / 128, Bb * 8 * 8), 256, DSMF>>>(out);
}

// round 12
// speedup vs baseline: 5.5739x; 1.0860x over previous
#include <cuda_runtime.h>
#include <cuda_fp16.h>
#include <cstdint>

#define Bb 4
#define Cc 2048
#define Dd 1024
#define Kk 64
#define HK 512
#define HV 1024
#define Vd 128
#define Uu 256

#define STH 72                  // smem stride (halves), [m][k] tiles
#define TILEH (128 * STH)
#define VSTH 136                // smem stride (halves), [k][n] tiles
#define VTILEH (128 * VSTH)
#define BTILEH (64 * VSTH)      // 64-row [k][n] tile for k_projh

// ---------------------------------------------------------------------------
// Scratch — natural layouts (R7-validated consumer addressing)
// ---------------------------------------------------------------------------
__device__ __align__(16) __half g_Xh[(size_t)Bb * Cc * Dd];       // 16 MB
__device__ __align__(16) __half g_Wq[(size_t)Dd * HK];
__device__ __align__(16) __half g_Wk[(size_t)Dd * HK];
__device__ __align__(16) __half g_Wv[(size_t)Dd * HV];
__device__ __align__(16) __half g_Pq[(size_t)Bb * Cc * HK];
__device__ __align__(16) __half g_Pk[(size_t)Bb * Cc * HK];
__device__ __align__(16) __half g_Pv[(size_t)Bb * Cc * HV];
__device__ __align__(16) float g_invD[Bb * 8 * Cc];

// ---------------------------------------------------------------------------
__device__ __forceinline__ uint32_t pack2(float x, float y) {
    __half2 h = __floats2half2_rn(x, y);
    return *reinterpret_cast<uint32_t*>(&h);
}

__device__ __forceinline__ void mma16(float* c, const uint32_t* a, const uint32_t* b) {
    asm volatile(
        "mma.sync.aligned.m16n8k16.row.col.f32.f16.f16.f32 "
        "{%0,%1,%2,%3}, {%4,%5,%6,%7}, {%8,%9}, {%0,%1,%2,%3};"
        : "+f"(c[0]), "+f"(c[1]), "+f"(c[2]), "+f"(c[3])
        : "r"(a[0]), "r"(a[1]), "r"(a[2]), "r"(a[3]), "r"(b[0]), "r"(b[1]));
}

__device__ __forceinline__ void ldm4(uint32_t* r, uint32_t addr) {
    asm volatile(
        "ldmatrix.sync.aligned.m8n8.x4.shared.b16 {%0,%1,%2,%3}, [%4];"
        : "=r"(r[0]), "=r"(r[1]), "=r"(r[2]), "=r"(r[3]) : "r"(addr));
}

__device__ __forceinline__ void ldm4t(uint32_t* r, uint32_t addr) {
    asm volatile(
        "ldmatrix.sync.aligned.m8n8.x4.trans.shared.b16 {%0,%1,%2,%3}, [%4];"
        : "=r"(r[0]), "=r"(r[1]), "=r"(r[2]), "=r"(r[3]) : "r"(addr));
}

__device__ __forceinline__ uint32_t s2u(const void* p) {
    return (uint32_t)__cvta_generic_to_shared(p);
}

__device__ __forceinline__ void cpa16(uint32_t d, const void* s) {
    asm volatile("cp.async.cg.shared.global [%0], [%1], 16;" :: "r"(d), "l"(s));
}
__device__ __forceinline__ void cp_commit() {
    asm volatile("cp.async.commit_group;");
}
template <int N> __device__ __forceinline__ void cp_wait() {
    asm volatile("cp.async.wait_group %0;" :: "n"(N));
}

// 64-deep k-tile warp mma, A [m][STH] via ldm4, B [n][SB] via ldm4.  (R7)
template <int SB>
__device__ __forceinline__ void warp_mma64(const __half* As, const __half* Bs,
                                           float acc[2][8][4],
                                           int wy, int wx, int lane) {
    const uint32_t ab = s2u(As), bb = s2u(Bs);
    const int arow = wy * 32 + (lane & 15);
    const int kA = (lane >> 4) << 3;
    const int brow = wx * 64 + (lane & 7) + ((lane >> 4) << 3);
    const int kB = ((lane >> 3) & 1) << 3;
#pragma unroll
    for (int ks = 0; ks < 4; ks++) {
        uint32_t a[2][4];
        ldm4(a[0], ab + (uint32_t)((arow * STH + ks * 16 + kA) * 2));
        ldm4(a[1], ab + (uint32_t)(((arow + 16) * STH + ks * 16 + kA) * 2));
#pragma unroll
        for (int j = 0; j < 4; j++) {
            uint32_t b[4];
            ldm4(b, bb + (uint32_t)(((brow + j * 16) * SB + ks * 16 + kB) * 2));
            mma16(acc[0][2 * j], a[0], b);
            mma16(acc[0][2 * j + 1], a[0], b + 2);
            mma16(acc[1][2 * j], a[1], b);
            mma16(acc[1][2 * j + 1], a[1], b + 2);
        }
    }
}

// 64-deep k-tile warp mma, A [m][STH] via ldm4, B natural [k][SB] via ldm4t.
template <int SB>
__device__ __forceinline__ void warp_mma64t(const __half* As, const __half* Bs,
                                            float acc[2][8][4],
                                            int wy, int wx, int lane) {
    const uint32_t ab = s2u(As), bb = s2u(Bs);
    const int arow = wy * 32 + (lane & 15);
    const int kA = (lane >> 4) << 3;
    const int vkrow = (lane & 7) + (((lane >> 3) & 1) << 3);
    const int vcol = (lane >> 4) << 3;
#pragma unroll
    for (int ks = 0; ks < 4; ks++) {
        uint32_t a[2][4];
        ldm4(a[0], ab + (uint32_t)((arow * STH + ks * 16 + kA) * 2));
        ldm4(a[1], ab + (uint32_t)(((arow + 16) * STH + ks * 16 + kA) * 2));
#pragma unroll
        for (int j = 0; j < 4; j++) {
            uint32_t b[4];
            ldm4t(b, bb + (uint32_t)(((ks * 16 + vkrow) * SB + wx * 64 + j * 16 + vcol) * 2));
            mma16(acc[0][2 * j], a[0], b);
            mma16(acc[0][2 * j + 1], a[0], b + 2);
            mma16(acc[1][2 * j], a[1], b);
            mma16(acc[1][2 * j + 1], a[1], b + 2);
        }
    }
}

// ---------------------------------------------------------------------------
// Convert kernel: fp32 -> fp16, 2048 elems per block
// ---------------------------------------------------------------------------
__global__ void k_cvt(const float* __restrict__ src, __half* __restrict__ dst) {
    size_t i = ((size_t)blockIdx.x * 256 + threadIdx.x) * 8;
    float4 a = *(const float4*)(src + i);
    float4 b = *(const float4*)(src + i + 4);
    *(uint4*)(dst + i) = make_uint4(pack2(a.x, a.y), pack2(a.z, a.w),
                                    pack2(b.x, b.y), pack2(b.z, b.w));
}

// ---------------------------------------------------------------------------
// Kernel: half GEMM  P[8192,N] = Xh[8192,1024] @ Wh[1024,N]  (R11, validated)
// ---------------------------------------------------------------------------
extern __shared__ __align__(16) __half dsm[];

__global__ __launch_bounds__(256) void k_projh(const __half* __restrict__ X,
                                               const __half* __restrict__ W,
                                               __half* __restrict__ P, int N) {
    __half* Apb[2] = {dsm, dsm + TILEH};
    __half* Bpb[2] = {dsm + 2 * TILEH, dsm + 2 * TILEH + BTILEH};
    const int tid = threadIdx.x, lane = tid & 31, wid = tid >> 5;
    const int wy = wid & 3, wx = wid >> 2;
    const int m0 = blockIdx.y * 128, n0 = blockIdx.x * 128;

    float acc[2][8][4];
#pragma unroll
    for (int i = 0; i < 2; i++)
#pragma unroll
        for (int j = 0; j < 8; j++)
#pragma unroll
            for (int c = 0; c < 4; c++) acc[i][j][c] = 0.f;

    auto fill = [&](int k0, __half* a, __half* bs) {
#pragma unroll
        for (int p = 0; p < 4; p++) {
            int id = tid + 256 * p, r = id >> 3, c = id & 7;
            cpa16(s2u(a + r * STH + c * 8), X + (size_t)(m0 + r) * Dd + k0 + c * 8);
        }
#pragma unroll
        for (int p = 0; p < 4; p++) {
            int id = tid + 256 * p, r = id >> 4, c = id & 15;
            cpa16(s2u(bs + r * VSTH + c * 8), W + (size_t)(k0 + r) * N + n0 + c * 8);
        }
    };

    fill(0, Apb[0], Bpb[0]);
    cp_commit();

    const int NT = Dd / 64;
    for (int t = 0; t < NT; t++) {
        if (t + 1 < NT) {
            fill((t + 1) * 64, Apb[(t + 1) & 1], Bpb[(t + 1) & 1]);
            cp_commit();
            cp_wait<1>();
        } else {
            cp_wait<0>();
        }
        __syncthreads();
        warp_mma64t<VSTH>(Apb[t & 1], Bpb[t & 1], acc, wy, wx, lane);
        __syncthreads();
    }

    const int tg = lane & 3, rr = lane >> 2;
#pragma unroll
    for (int mf = 0; mf < 2; mf++) {
        int m = m0 + wy * 32 + mf * 16 + rr;
#pragma unroll
        for (int nf = 0; nf < 8; nf++) {
            int n = n0 + wx * 64 + nf * 8 + tg * 2;
            *(uint32_t*)(P + (size_t)m * N + n) = pack2(acc[mf][nf][0], acc[mf][nf][1]);
            *(uint32_t*)(P + (size_t)(m + 8) * N + n) = pack2(acc[mf][nf][2], acc[mf][nf][3]);
        }
    }
}

// ---------------------------------------------------------------------------
// Kernel 2 (R7 verbatim): invD[z][c2] = 1/sum_q exp(S/8).
// ---------------------------------------------------------------------------
__global__ __launch_bounds__(256) void k_sums() {
    __half* As = dsm;
    __half* Bs[2] = {dsm + TILEH, dsm + 2 * TILEH};
    float* sD = (float*)(dsm + 3 * TILEH);
    const int tid = threadIdx.x, lane = tid & 31, wid = tid >> 5;
    const int wy = wid & 3, wx = wid >> 2;
    const int tg = lane & 3, rr = lane >> 2;
    const int z = blockIdx.y;
    const int c20 = blockIdx.x * 128;
    const __half* Kh = g_Pk + (size_t)z * Cc * Kk;
    const __half* Qh = g_Pq + (size_t)z * Cc * Kk;

    if (tid < 128) sD[tid] = 0.f;

#pragma unroll
    for (int p = 0; p < 4; p++) {
        int id = tid + 256 * p, r = id >> 3, c = id & 7;
        cpa16(s2u(As + r * STH + c * 8), Kh + (size_t)(c20 + r) * Kk + c * 8);
        cpa16(s2u(Bs[0] + r * STH + c * 8), Qh + (size_t)r * Kk + c * 8);
    }
    cp_commit();

    float rs[2][2] = {{0.f, 0.f}, {0.f, 0.f}};
    const int NT = Cc / 128;
    for (int t = 0; t < NT; t++) {
        __syncthreads();
        if (t + 1 < NT) {
            const __half* src = Qh + (size_t)(t + 1) * 128 * Kk;
            __half* dst = Bs[(t + 1) & 1];
#pragma unroll
            for (int p = 0; p < 4; p++) {
                int id = tid + 256 * p, r = id >> 3, c = id & 7;
                cpa16(s2u(dst + r * STH + c * 8), src + (size_t)r * Kk + c * 8);
            }
            cp_commit();
            cp_wait<1>();
        } else {
            cp_wait<0>();
        }
        __syncthreads();

        float acc[2][8][4];
#pragma unroll
        for (int i = 0; i < 2; i++)
#pragma unroll
            for (int j = 0; j < 8; j++)
#pragma unroll
                for (int c = 0; c < 4; c++) acc[i][j][c] = 0.f;
        warp_mma64<STH>(As, Bs[t & 1], acc, wy, wx, lane);
#pragma unroll
        for (int mf = 0; mf < 2; mf++)
#pragma unroll
            for (int nf = 0; nf < 8; nf++) {
                rs[mf][0] += __expf(acc[mf][nf][0] * 0.125f)
                           + __expf(acc[mf][nf][1] * 0.125f);
                rs[mf][1] += __expf(acc[mf][nf][2] * 0.125f)
                           + __expf(acc[mf][nf][3] * 0.125f);
            }
    }
#pragma unroll
    for (int mf = 0; mf < 2; mf++)
#pragma unroll
        for (int h2 = 0; h2 < 2; h2++) {
            float s = rs[mf][h2];
            s += __shfl_xor_sync(0xffffffffu, s, 1);
            s += __shfl_xor_sync(0xffffffffu, s, 2);
            if (tg == 0)
                atomicAdd(&sD[wy * 32 + mf * 16 + h2 * 8 + rr], s);
        }
    __syncthreads();
    if (tid < 128) g_invD[z * Cc + c20 + tid] = 1.0f / sD[tid];
}

// ---------------------------------------------------------------------------
// Kernel 3: fused scores+softmax+PV, 32 u1-rows per warp (one CTA per w).
// Quarter-interleaved: GEMM1(32 c2) -> exp*invD -> GEMM2(those 2 kb chunks),
// bounding live registers while halving cross-warp B-fragment redundancy.
// ---------------------------------------------------------------------------
__global__ __launch_bounds__(256, 1) void k_fused(float* __restrict__ out) {
    __half* Ks[2] = {dsm, dsm + TILEH};
    __half* Vs[2] = {dsm + 2 * TILEH, dsm + 2 * TILEH + VTILEH};
    float* iDs[2] = {(float*)(dsm + 2 * TILEH + 2 * VTILEH),
                     (float*)(dsm + 2 * TILEH + 2 * VTILEH) + 128};
    const int tid = threadIdx.x, lane = tid & 31, wid = tid >> 5;
    const int tg = lane & 3, rr = lane >> 2;
    const int w = blockIdx.x;
    const int b = w >> 6, h = (w >> 3) & 7, hp = w & 7, z = w >> 3;
    const __half* Qh = g_Pq + (size_t)z * Cc * Kk;
    const __half* Kh = g_Pk + (size_t)z * Cc * Kk;
    const __half* Bv = g_Pv + (size_t)b * Cc * HV + (size_t)hp * Uu * HV;
    const float* iD = g_invD + z * Cc;

    // Q fragments: 32 rows per warp, u1 = wid*32 + mf*16 + {rr, rr+8}
    const int u1b = wid * 32 + rr;
    const __half* Qbase = Qh + (size_t)(8 * u1b + hp) * Kk;
    uint32_t Qa[2][4][4];
#pragma unroll
    for (int mf = 0; mf < 2; mf++) {
        const __half* Q0 = Qbase + (size_t)(mf * 128) * Kk;   // +16 rows = +128*Kk
        const __half* Q1 = Q0 + (size_t)64 * Kk;              // +8 rows
#pragma unroll
        for (int ks = 0; ks < 4; ks++) {
            Qa[mf][ks][0] = *(const uint32_t*)(Q0 + ks * 16 + 2 * tg);
            Qa[mf][ks][1] = *(const uint32_t*)(Q1 + ks * 16 + 2 * tg);
            Qa[mf][ks][2] = *(const uint32_t*)(Q0 + ks * 16 + 8 + 2 * tg);
            Qa[mf][ks][3] = *(const uint32_t*)(Q1 + ks * 16 + 8 + 2 * tg);
        }
    }

    float of[2][16][4];
#pragma unroll
    for (int mf = 0; mf < 2; mf++)
#pragma unroll
        for (int j = 0; j < 16; j++)
#pragma unroll
            for (int c = 0; c < 4; c++) of[mf][j][c] = 0.f;

    auto fill = [&](int c20, __half* ks, __half* vs, float* ids) {
#pragma unroll
        for (int p = 0; p < 4; p++) {
            int id = tid + 256 * p, r = id >> 3, c = id & 7;
            cpa16(s2u(ks + r * STH + c * 8), Kh + (size_t)(c20 + r) * Kk + c * 8);
        }
#pragma unroll
        for (int p = 0; p < 8; p++) {
            int id = tid + 256 * p, r = id >> 4, c = id & 15;
            cpa16(s2u(vs + r * VSTH + c * 8), Bv + (size_t)(c20 + r) * Vd + c * 8);
        }
        if (tid < 32) cpa16(s2u(ids + tid * 4), iD + c20 + tid * 4);
    };

    fill(0, Ks[0], Vs[0], iDs[0]);
    cp_commit();

    const int brow = (lane & 7) + ((lane >> 4) << 3);
    const int kB = ((lane >> 3) & 1) << 3;
    const int vkrow = (lane & 7) + (((lane >> 3) & 1) << 3);
    const int vcol = (lane >> 4) << 3;

    const int NT = Cc / 128;
    for (int t = 0; t < NT; t++) {
        __syncthreads();
        if (t + 1 < NT) {
            fill((t + 1) * 128, Ks[(t + 1) & 1], Vs[(t + 1) & 1], iDs[(t + 1) & 1]);
            cp_commit();
            cp_wait<1>();
        } else {
            cp_wait<0>();
        }
        __syncthreads();

        const uint32_t ksb = s2u(Ks[t & 1]), vsb = s2u(Vs[t & 1]);
        const float* ids = iDs[t & 1];

#pragma unroll
        for (int qtr = 0; qtr < 4; qtr++) {
            // GEMM1 for c2 quarter [qtr*32, qtr*32+32): cf[mf][nfl][4]
            float cf[2][4][4];
#pragma unroll
            for (int mf = 0; mf < 2; mf++)
#pragma unroll
                for (int n = 0; n < 4; n++)
#pragma unroll
                    for (int c = 0; c < 4; c++) cf[mf][n][c] = 0.f;
#pragma unroll
            for (int ks = 0; ks < 4; ks++) {
#pragma unroll
                for (int jj = 0; jj < 2; jj++) {
                    int j = qtr * 2 + jj;
                    uint32_t bfr[4];
                    ldm4(bfr, ksb + (uint32_t)(((j * 16 + brow) * STH + ks * 16 + kB) * 2));
                    mma16(cf[0][2 * jj], Qa[0][ks], bfr);
                    mma16(cf[0][2 * jj + 1], Qa[0][ks], bfr + 2);
                    mma16(cf[1][2 * jj], Qa[1][ks], bfr);
                    mma16(cf[1][2 * jj + 1], Qa[1][ks], bfr + 2);
                }
            }

            // exp * invD -> fp16 A-frags for this quarter (2 kb chunks)
            uint32_t ak[2][2][4];
#pragma unroll
            for (int mf = 0; mf < 2; mf++)
#pragma unroll
                for (int nfl = 0; nfl < 4; nfl++) {
                    int nfg = qtr * 4 + nfl;
                    float2 idv = *(const float2*)(ids + nfg * 8 + 2 * tg);
                    float e0 = __expf(cf[mf][nfl][0] * 0.125f) * idv.x;
                    float e1 = __expf(cf[mf][nfl][1] * 0.125f) * idv.y;
                    float e2 = __expf(cf[mf][nfl][2] * 0.125f) * idv.x;
                    float e3 = __expf(cf[mf][nfl][3] * 0.125f) * idv.y;
                    ak[mf][nfl >> 1][(nfl & 1) * 2 + 0] = pack2(e0, e1);
                    ak[mf][nfl >> 1][(nfl & 1) * 2 + 1] = pack2(e2, e3);
                }

            // GEMM2 partial: kb = qtr*2 + {0,1}, full d (8 j-groups)
#pragma unroll
            for (int kk = 0; kk < 2; kk++) {
                int kb = qtr * 2 + kk;
#pragma unroll
                for (int j = 0; j < 8; j++) {
                    uint32_t bfr[4];
                    ldm4t(bfr, vsb + (uint32_t)(((kb * 16 + vkrow) * VSTH + j * 16 + vcol) * 2));
                    mma16(of[0][2 * j], ak[0][kk], bfr);
                    mma16(of[0][2 * j + 1], ak[0][kk], bfr + 2);
                    mma16(of[1][2 * j], ak[1][kk], bfr);
                    mma16(of[1][2 * j + 1], ak[1][kk], bfr + 2);
                }
            }
        }
    }

    // epilogue: rows c1 = h*256 + u1, cols hp*128 + d
#pragma unroll
    for (int mf = 0; mf < 2; mf++) {
        int u1 = wid * 32 + mf * 16 + rr;
        float* g0 = out + ((size_t)b * Cc + h * Uu + u1) * HV + hp * Vd;
        float* g1 = g0 + (size_t)8 * HV;
#pragma unroll
        for (int df = 0; df < 16; df++) {
            int d = df * 8 + 2 * tg;
            *(float2*)(g0 + d) = make_float2(of[mf][df][0], of[mf][df][1]);
            *(float2*)(g1 + d) = make_float2(of[mf][df][2], of[mf][df][3]);
        }
    }
}

// ---------------------------------------------------------------------------
extern "C" void kernel_launch(void* const* d_in, const int* in_sizes, int n_in,
                              void* d_out, int out_size) {
    (void)in_sizes; (void)n_in; (void)out_size;
    const float* x  = (const float*)d_in[0];
    const float* Mq = (const float*)d_in[1];
    const float* Mk = (const float*)d_in[2];
    const float* Mv = (const float*)d_in[3];
    float* out = (float*)d_out;

    __half *pXh, *pWq, *pWk, *pWv, *pPq, *pPk, *pPv;
    cudaGetSymbolAddress((void**)&pXh, g_Xh);
    cudaGetSymbolAddress((void**)&pWq, g_Wq);
    cudaGetSymbolAddress((void**)&pWk, g_Wk);
    cudaGetSymbolAddress((void**)&pWv, g_Wv);
    cudaGetSymbolAddress((void**)&pPq, g_Pq);
    cudaGetSymbolAddress((void**)&pPk, g_Pk);
    cudaGetSymbolAddress((void**)&pPv, g_Pv);

    const int DSMP = (2 * TILEH + 2 * BTILEH) * sizeof(__half);          // 71680
    const int DSMS = 3 * TILEH * sizeof(__half) + 512;                   // 55808
    const int DSMF = (2 * TILEH + 2 * VTILEH) * sizeof(__half) + 1024;   // 107520
    static bool attr_done = false;
    if (!attr_done) {
        cudaFuncSetAttribute(k_projh, cudaFuncAttributeMaxDynamicSharedMemorySize, DSMP);
        cudaFuncSetAttribute(k_sums, cudaFuncAttributeMaxDynamicSharedMemorySize, DSMS);
        cudaFuncSetAttribute(k_fused, cudaFuncAttributeMaxDynamicSharedMemorySize, DSMF);
        attr_done = true;
    }

    // convert pass (all fp32 -> fp16)
    k_cvt<<<(int)(((size_t)Bb * Cc * Dd) / 2048), 256>>>(x, pXh);
    k_cvt<<<(Dd * HK) / 2048, 256>>>(Mq, pWq);
    k_cvt<<<(Dd * HK) / 2048, 256>>>(Mk, pWk);
    k_cvt<<<(int)(((size_t)Dd * HV) / 2048), 256>>>(Mv, pWv);

    // projections (natural layouts; consumers use flat-chunk addressing)
    k_projh<<<dim3(HK / 128, (Bb * Cc) / 128), 256, DSMP>>>(pXh, pWq, pPq, HK);
    k_projh<<<dim3(HK / 128, (Bb * Cc) / 128), 256, DSMP>>>(pXh, pWk, pPk, HK);
    k_projh<<<dim3(HV / 128, (Bb * Cc) / 128), 256, DSMP>>>(pXh, pWv, pPv, HV);

    k_sums<<<dim3(Cc / 128, Bb * 8), 256, DSMS>>>();
    k_fused<<<Bb * 8 * 8, 256, DSMF>>>(out);
}

// round 13
// speedup vs baseline: 5.5920x; 1.0033x over previous
#include <cuda_runtime.h>
#include <cuda_fp16.h>
#include <cstdint>

#define Bb 4
#define Cc 2048
#define Dd 1024
#define Kk 64
#define HK 512
#define HV 1024
#define Vd 128
#define Uu 256

#define STH 72                  // smem stride (halves), [m][k] tiles
#define TILEH (128 * STH)
#define VSTH 136                // smem stride (halves), [k][n] tiles
#define VTILEH (128 * VSTH)
#define BTILEH (64 * VSTH)      // 64-row [k][n] tile for k_projh

#define KE 0.18033688f          // 0.125 * log2(e)

// ---------------------------------------------------------------------------
// Scratch — natural layouts (R7-validated consumer addressing)
// ---------------------------------------------------------------------------
__device__ __align__(16) __half g_Xh[(size_t)Bb * Cc * Dd];       // 16 MB
__device__ __align__(16) __half g_Wq[(size_t)Dd * HK];
__device__ __align__(16) __half g_Wk[(size_t)Dd * HK];
__device__ __align__(16) __half g_Wv[(size_t)Dd * HV];
__device__ __align__(16) __half g_Pq[(size_t)Bb * Cc * HK];
__device__ __align__(16) __half g_Pk[(size_t)Bb * Cc * HK];
__device__ __align__(16) __half g_Pv[(size_t)Bb * Cc * HV];
__device__ __align__(16) float g_invD[Bb * 8 * Cc];   // holds -log2(D)

// ---------------------------------------------------------------------------
__device__ __forceinline__ uint32_t pack2(float x, float y) {
    __half2 h = __floats2half2_rn(x, y);
    return *reinterpret_cast<uint32_t*>(&h);
}

__device__ __forceinline__ float ex2(float x) {
    float y;
    asm("ex2.approx.f32 %0, %1;" : "=f"(y) : "f"(x));
    return y;
}

__device__ __forceinline__ void mma16(float* c, const uint32_t* a, const uint32_t* b) {
    asm volatile(
        "mma.sync.aligned.m16n8k16.row.col.f32.f16.f16.f32 "
        "{%0,%1,%2,%3}, {%4,%5,%6,%7}, {%8,%9}, {%0,%1,%2,%3};"
        : "+f"(c[0]), "+f"(c[1]), "+f"(c[2]), "+f"(c[3])
        : "r"(a[0]), "r"(a[1]), "r"(a[2]), "r"(a[3]), "r"(b[0]), "r"(b[1]));
}

__device__ __forceinline__ void ldm4(uint32_t* r, uint32_t addr) {
    asm volatile(
        "ldmatrix.sync.aligned.m8n8.x4.shared.b16 {%0,%1,%2,%3}, [%4];"
        : "=r"(r[0]), "=r"(r[1]), "=r"(r[2]), "=r"(r[3]) : "r"(addr));
}

__device__ __forceinline__ void ldm4t(uint32_t* r, uint32_t addr) {
    asm volatile(
        "ldmatrix.sync.aligned.m8n8.x4.trans.shared.b16 {%0,%1,%2,%3}, [%4];"
        : "=r"(r[0]), "=r"(r[1]), "=r"(r[2]), "=r"(r[3]) : "r"(addr));
}

__device__ __forceinline__ uint32_t s2u(const void* p) {
    return (uint32_t)__cvta_generic_to_shared(p);
}

__device__ __forceinline__ void cpa16(uint32_t d, const void* s) {
    asm volatile("cp.async.cg.shared.global [%0], [%1], 16;" :: "r"(d), "l"(s));
}
__device__ __forceinline__ void cp_commit() {
    asm volatile("cp.async.commit_group;");
}
template <int N> __device__ __forceinline__ void cp_wait() {
    asm volatile("cp.async.wait_group %0;" :: "n"(N));
}

// 64-deep k-tile warp mma, A [m][STH] via ldm4, B [n][SB] via ldm4.  (R7)
template <int SB>
__device__ __forceinline__ void warp_mma64(const __half* As, const __half* Bs,
                                           float acc[2][8][4],
                                           int wy, int wx, int lane) {
    const uint32_t ab = s2u(As), bb = s2u(Bs);
    const int arow = wy * 32 + (lane & 15);
    const int kA = (lane >> 4) << 3;
    const int brow = wx * 64 + (lane & 7) + ((lane >> 4) << 3);
    const int kB = ((lane >> 3) & 1) << 3;
#pragma unroll
    for (int ks = 0; ks < 4; ks++) {
        uint32_t a[2][4];
        ldm4(a[0], ab + (uint32_t)((arow * STH + ks * 16 + kA) * 2));
        ldm4(a[1], ab + (uint32_t)(((arow + 16) * STH + ks * 16 + kA) * 2));
#pragma unroll
        for (int j = 0; j < 4; j++) {
            uint32_t b[4];
            ldm4(b, bb + (uint32_t)(((brow + j * 16) * SB + ks * 16 + kB) * 2));
            mma16(acc[0][2 * j], a[0], b);
            mma16(acc[0][2 * j + 1], a[0], b + 2);
            mma16(acc[1][2 * j], a[1], b);
            mma16(acc[1][2 * j + 1], a[1], b + 2);
        }
    }
}

// 64-deep k-tile warp mma, A [m][STH] via ldm4, B natural [k][SB] via ldm4t.
template <int SB>
__device__ __forceinline__ void warp_mma64t(const __half* As, const __half* Bs,
                                            float acc[2][8][4],
                                            int wy, int wx, int lane) {
    const uint32_t ab = s2u(As), bb = s2u(Bs);
    const int arow = wy * 32 + (lane & 15);
    const int kA = (lane >> 4) << 3;
    const int vkrow = (lane & 7) + (((lane >> 3) & 1) << 3);
    const int vcol = (lane >> 4) << 3;
#pragma unroll
    for (int ks = 0; ks < 4; ks++) {
        uint32_t a[2][4];
        ldm4(a[0], ab + (uint32_t)((arow * STH + ks * 16 + kA) * 2));
        ldm4(a[1], ab + (uint32_t)(((arow + 16) * STH + ks * 16 + kA) * 2));
#pragma unroll
        for (int j = 0; j < 4; j++) {
            uint32_t b[4];
            ldm4t(b, bb + (uint32_t)(((ks * 16 + vkrow) * SB + wx * 64 + j * 16 + vcol) * 2));
            mma16(acc[0][2 * j], a[0], b);
            mma16(acc[0][2 * j + 1], a[0], b + 2);
            mma16(acc[1][2 * j], a[1], b);
            mma16(acc[1][2 * j + 1], a[1], b + 2);
        }
    }
}

// ---------------------------------------------------------------------------
// Convert kernel: fp32 -> fp16, 2048 elems per block
// ---------------------------------------------------------------------------
__global__ void k_cvt(const float* __restrict__ src, __half* __restrict__ dst) {
    size_t i = ((size_t)blockIdx.x * 256 + threadIdx.x) * 8;
    float4 a = *(const float4*)(src + i);
    float4 b = *(const float4*)(src + i + 4);
    *(uint4*)(dst + i) = make_uint4(pack2(a.x, a.y), pack2(a.z, a.w),
                                    pack2(b.x, b.y), pack2(b.z, b.w));
}

// ---------------------------------------------------------------------------
// Kernel: half GEMM  P[8192,N] = Xh[8192,1024] @ Wh[1024,N]  (R11, validated)
// ---------------------------------------------------------------------------
extern __shared__ __align__(16) __half dsm[];

__global__ __launch_bounds__(256) void k_projh(const __half* __restrict__ X,
                                               const __half* __restrict__ W,
                                               __half* __restrict__ P, int N) {
    __half* Apb[2] = {dsm, dsm + TILEH};
    __half* Bpb[2] = {dsm + 2 * TILEH, dsm + 2 * TILEH + BTILEH};
    const int tid = threadIdx.x, lane = tid & 31, wid = tid >> 5;
    const int wy = wid & 3, wx = wid >> 2;
    const int m0 = blockIdx.y * 128, n0 = blockIdx.x * 128;

    float acc[2][8][4];
#pragma unroll
    for (int i = 0; i < 2; i++)
#pragma unroll
        for (int j = 0; j < 8; j++)
#pragma unroll
            for (int c = 0; c < 4; c++) acc[i][j][c] = 0.f;

    auto fill = [&](int k0, __half* a, __half* bs) {
#pragma unroll
        for (int p = 0; p < 4; p++) {
            int id = tid + 256 * p, r = id >> 3, c = id & 7;
            cpa16(s2u(a + r * STH + c * 8), X + (size_t)(m0 + r) * Dd + k0 + c * 8);
        }
#pragma unroll
        for (int p = 0; p < 4; p++) {
            int id = tid + 256 * p, r = id >> 4, c = id & 15;
            cpa16(s2u(bs + r * VSTH + c * 8), W + (size_t)(k0 + r) * N + n0 + c * 8);
        }
    };

    fill(0, Apb[0], Bpb[0]);
    cp_commit();

    const int NT = Dd / 64;
    for (int t = 0; t < NT; t++) {
        if (t + 1 < NT) {
            fill((t + 1) * 64, Apb[(t + 1) & 1], Bpb[(t + 1) & 1]);
            cp_commit();
            cp_wait<1>();
        } else {
            cp_wait<0>();
        }
        __syncthreads();
        warp_mma64t<VSTH>(Apb[t & 1], Bpb[t & 1], acc, wy, wx, lane);
        __syncthreads();
    }

    const int tg = lane & 3, rr = lane >> 2;
#pragma unroll
    for (int mf = 0; mf < 2; mf++) {
        int m = m0 + wy * 32 + mf * 16 + rr;
#pragma unroll
        for (int nf = 0; nf < 8; nf++) {
            int n = n0 + wx * 64 + nf * 8 + tg * 2;
            *(uint32_t*)(P + (size_t)m * N + n) = pack2(acc[mf][nf][0], acc[mf][nf][1]);
            *(uint32_t*)(P + (size_t)(m + 8) * N + n) = pack2(acc[mf][nf][2], acc[mf][nf][3]);
        }
    }
}

// ---------------------------------------------------------------------------
// Kernel 2: g_invD[z][c2] = -log2(sum_q exp(S/8))
// ---------------------------------------------------------------------------
__global__ __launch_bounds__(256) void k_sums() {
    __half* As = dsm;
    __half* Bs[2] = {dsm + TILEH, dsm + 2 * TILEH};
    float* sD = (float*)(dsm + 3 * TILEH);
    const int tid = threadIdx.x, lane = tid & 31, wid = tid >> 5;
    const int wy = wid & 3, wx = wid >> 2;
    const int tg = lane & 3, rr = lane >> 2;
    const int z = blockIdx.y;
    const int c20 = blockIdx.x * 128;
    const __half* Kh = g_Pk + (size_t)z * Cc * Kk;
    const __half* Qh = g_Pq + (size_t)z * Cc * Kk;

    if (tid < 128) sD[tid] = 0.f;

#pragma unroll
    for (int p = 0; p < 4; p++) {
        int id = tid + 256 * p, r = id >> 3, c = id & 7;
        cpa16(s2u(As + r * STH + c * 8), Kh + (size_t)(c20 + r) * Kk + c * 8);
        cpa16(s2u(Bs[0] + r * STH + c * 8), Qh + (size_t)r * Kk + c * 8);
    }
    cp_commit();

    float rs[2][2] = {{0.f, 0.f}, {0.f, 0.f}};
    const int NT = Cc / 128;
    for (int t = 0; t < NT; t++) {
        __syncthreads();
        if (t + 1 < NT) {
            const __half* src = Qh + (size_t)(t + 1) * 128 * Kk;
            __half* dst = Bs[(t + 1) & 1];
#pragma unroll
            for (int p = 0; p < 4; p++) {
                int id = tid + 256 * p, r = id >> 3, c = id & 7;
                cpa16(s2u(dst + r * STH + c * 8), src + (size_t)r * Kk + c * 8);
            }
            cp_commit();
            cp_wait<1>();
        } else {
            cp_wait<0>();
        }
        __syncthreads();

        float acc[2][8][4];
#pragma unroll
        for (int i = 0; i < 2; i++)
#pragma unroll
            for (int j = 0; j < 8; j++)
#pragma unroll
                for (int c = 0; c < 4; c++) acc[i][j][c] = 0.f;
        warp_mma64<STH>(As, Bs[t & 1], acc, wy, wx, lane);
#pragma unroll
        for (int mf = 0; mf < 2; mf++)
#pragma unroll
            for (int nf = 0; nf < 8; nf++) {
                rs[mf][0] += __expf(acc[mf][nf][0] * 0.125f)
                           + __expf(acc[mf][nf][1] * 0.125f);
                rs[mf][1] += __expf(acc[mf][nf][2] * 0.125f)
                           + __expf(acc[mf][nf][3] * 0.125f);
            }
    }
#pragma unroll
    for (int mf = 0; mf < 2; mf++)
#pragma unroll
        for (int h2 = 0; h2 < 2; h2++) {
            float s = rs[mf][h2];
            s += __shfl_xor_sync(0xffffffffu, s, 1);
            s += __shfl_xor_sync(0xffffffffu, s, 2);
            if (tg == 0)
                atomicAdd(&sD[wy * 32 + mf * 16 + h2 * 8 + rr], s);
        }
    __syncthreads();
    if (tid < 128) g_invD[z * Cc + c20 + tid] = -__log2f(sD[tid]);
}

// ---------------------------------------------------------------------------
// Kernel 3: fused scores+softmax+PV.  128 threads, 4 warps, 128 u1 per CTA,
// 2 CTAs/SM.  e = ex2(s*KE + L[c2])  (L = -log2 D, fused scale).
// ---------------------------------------------------------------------------
__global__ __launch_bounds__(128, 2) void k_fused(float* __restrict__ out) {
    __half* Ks[2] = {dsm, dsm + TILEH};
    __half* Vs[2] = {dsm + 2 * TILEH, dsm + 2 * TILEH + VTILEH};
    float* iDs[2] = {(float*)(dsm + 2 * TILEH + 2 * VTILEH),
                     (float*)(dsm + 2 * TILEH + 2 * VTILEH) + 128};
    const int tid = threadIdx.x, lane = tid & 31, wid = tid >> 5;
    const int tg = lane & 3, rr = lane >> 2;
    const int u1t = blockIdx.x;                       // 0 or 1
    const int w = blockIdx.y;
    const int b = w >> 6, h = (w >> 3) & 7, hp = w & 7, z = w >> 3;
    const __half* Qh = g_Pq + (size_t)z * Cc * Kk;
    const __half* Kh = g_Pk + (size_t)z * Cc * Kk;
    const __half* Bv = g_Pv + (size_t)b * Cc * HV + (size_t)hp * Uu * HV;
    const float* iD = g_invD + z * Cc;

    // Q fragments: 32 rows per warp, u1 = u1t*128 + wid*32 + mf*16 + {rr, rr+8}
    const int u1b = u1t * 128 + wid * 32 + rr;
    const __half* Qbase = Qh + (size_t)(8 * u1b + hp) * Kk;
    uint32_t Qa[2][4][4];
#pragma unroll
    for (int mf = 0; mf < 2; mf++) {
        const __half* Q0 = Qbase + (size_t)(mf * 128) * Kk;
        const __half* Q1 = Q0 + (size_t)64 * Kk;
#pragma unroll
        for (int ks = 0; ks < 4; ks++) {
            Qa[mf][ks][0] = *(const uint32_t*)(Q0 + ks * 16 + 2 * tg);
            Qa[mf][ks][1] = *(const uint32_t*)(Q1 + ks * 16 + 2 * tg);
            Qa[mf][ks][2] = *(const uint32_t*)(Q0 + ks * 16 + 8 + 2 * tg);
            Qa[mf][ks][3] = *(const uint32_t*)(Q1 + ks * 16 + 8 + 2 * tg);
        }
    }

    float of[2][16][4];
#pragma unroll
    for (int mf = 0; mf < 2; mf++)
#pragma unroll
        for (int j = 0; j < 16; j++)
#pragma unroll
            for (int c = 0; c < 4; c++) of[mf][j][c] = 0.f;

    auto fill = [&](int c20, __half* ks, __half* vs, float* ids) {
#pragma unroll
        for (int p = 0; p < 8; p++) {
            int id = tid + 128 * p, r = id >> 3, c = id & 7;
            cpa16(s2u(ks + r * STH + c * 8), Kh + (size_t)(c20 + r) * Kk + c * 8);
        }
#pragma unroll
        for (int p = 0; p < 16; p++) {
            int id = tid + 128 * p, r = id >> 4, c = id & 15;
            cpa16(s2u(vs + r * VSTH + c * 8), Bv + (size_t)(c20 + r) * Vd + c * 8);
        }
        if (tid < 32) cpa16(s2u(ids + tid * 4), iD + c20 + tid * 4);
    };

    fill(0, Ks[0], Vs[0], iDs[0]);
    cp_commit();

    const int brow = (lane & 7) + ((lane >> 4) << 3);
    const int kB = ((lane >> 3) & 1) << 3;
    const int vkrow = (lane & 7) + (((lane >> 3) & 1) << 3);
    const int vcol = (lane >> 4) << 3;

    const int NT = Cc / 128;
    for (int t = 0; t < NT; t++) {
        __syncthreads();
        if (t + 1 < NT) {
            fill((t + 1) * 128, Ks[(t + 1) & 1], Vs[(t + 1) & 1], iDs[(t + 1) & 1]);
            cp_commit();
            cp_wait<1>();
        } else {
            cp_wait<0>();
        }
        __syncthreads();

        const uint32_t ksb = s2u(Ks[t & 1]), vsb = s2u(Vs[t & 1]);
        const float* ids = iDs[t & 1];

#pragma unroll
        for (int qtr = 0; qtr < 4; qtr++) {
            float cf[2][4][4];
#pragma unroll
            for (int mf = 0; mf < 2; mf++)
#pragma unroll
                for (int n = 0; n < 4; n++)
#pragma unroll
                    for (int c = 0; c < 4; c++) cf[mf][n][c] = 0.f;
#pragma unroll
            for (int ks = 0; ks < 4; ks++) {
#pragma unroll
                for (int jj = 0; jj < 2; jj++) {
                    int j = qtr * 2 + jj;
                    uint32_t bfr[4];
                    ldm4(bfr, ksb + (uint32_t)(((j * 16 + brow) * STH + ks * 16 + kB) * 2));
                    mma16(cf[0][2 * jj], Qa[0][ks], bfr);
                    mma16(cf[0][2 * jj + 1], Qa[0][ks], bfr + 2);
                    mma16(cf[1][2 * jj], Qa[1][ks], bfr);
                    mma16(cf[1][2 * jj + 1], Qa[1][ks], bfr + 2);
                }
            }

            uint32_t ak[2][2][4];
#pragma unroll
            for (int mf = 0; mf < 2; mf++)
#pragma unroll
                for (int nfl = 0; nfl < 4; nfl++) {
                    int nfg = qtr * 4 + nfl;
                    float2 Lv = *(const float2*)(ids + nfg * 8 + 2 * tg);
                    float e0 = ex2(fmaf(cf[mf][nfl][0], KE, Lv.x));
                    float e1 = ex2(fmaf(cf[mf][nfl][1], KE, Lv.y));
                    float e2 = ex2(fmaf(cf[mf][nfl][2], KE, Lv.x));
                    float e3 = ex2(fmaf(cf[mf][nfl][3], KE, Lv.y));
                    ak[mf][nfl >> 1][(nfl & 1) * 2 + 0] = pack2(e0, e1);
                    ak[mf][nfl >> 1][(nfl & 1) * 2 + 1] = pack2(e2, e3);
                }

#pragma unroll
            for (int kk = 0; kk < 2; kk++) {
                int kb = qtr * 2 + kk;
#pragma unroll
                for (int j = 0; j < 8; j++) {
                    uint32_t bfr[4];
                    ldm4t(bfr, vsb + (uint32_t)(((kb * 16 + vkrow) * VSTH + j * 16 + vcol) * 2));
                    mma16(of[0][2 * j], ak[0][kk], bfr);
                    mma16(of[0][2 * j + 1], ak[0][kk], bfr + 2);
                    mma16(of[1][2 * j], ak[1][kk], bfr);
                    mma16(of[1][2 * j + 1], ak[1][kk], bfr + 2);
                }
            }
        }
    }

#pragma unroll
    for (int mf = 0; mf < 2; mf++) {
        int u1 = u1t * 128 + wid * 32 + mf * 16 + rr;
        float* g0 = out + ((size_t)b * Cc + h * Uu + u1) * HV + hp * Vd;
        float* g1 = g0 + (size_t)8 * HV;
#pragma unroll
        for (int df = 0; df < 16; df++) {
            int d = df * 8 + 2 * tg;
            *(float2*)(g0 + d) = make_float2(of[mf][df][0], of[mf][df][1]);
            *(float2*)(g1 + d) = make_float2(of[mf][df][2], of[mf][df][3]);
        }
    }
}

// ---------------------------------------------------------------------------
extern "C" void kernel_launch(void* const* d_in, const int* in_sizes, int n_in,
                              void* d_out, int out_size) {
    (void)in_sizes; (void)n_in; (void)out_size;
    const float* x  = (const float*)d_in[0];
    const float* Mq = (const float*)d_in[1];
    const float* Mk = (const float*)d_in[2];
    const float* Mv = (const float*)d_in[3];
    float* out = (float*)d_out;

    __half *pXh, *pWq, *pWk, *pWv, *pPq, *pPk, *pPv;
    cudaGetSymbolAddress((void**)&pXh, g_Xh);
    cudaGetSymbolAddress((void**)&pWq, g_Wq);
    cudaGetSymbolAddress((void**)&pWk, g_Wk);
    cudaGetSymbolAddress((void**)&pWv, g_Wv);
    cudaGetSymbolAddress((void**)&pPq, g_Pq);
    cudaGetSymbolAddress((void**)&pPk, g_Pk);
    cudaGetSymbolAddress((void**)&pPv, g_Pv);

    const int DSMP = (2 * TILEH + 2 * BTILEH) * sizeof(__half);          // 71680
    const int DSMS = 3 * TILEH * sizeof(__half) + 512;                   // 55808
    const int DSMF = (2 * TILEH + 2 * VTILEH) * sizeof(__half) + 1024;   // 107520
    static bool attr_done = false;
    if (!attr_done) {
        cudaFuncSetAttribute(k_projh, cudaFuncAttributeMaxDynamicSharedMemorySize, DSMP);
        cudaFuncSetAttribute(k_sums, cudaFuncAttributeMaxDynamicSharedMemorySize, DSMS);
        cudaFuncSetAttribute(k_fused, cudaFuncAttributeMaxDynamicSharedMemorySize, DSMF);
        attr_done = true;
    }

    // convert pass (all fp32 -> fp16)
    k_cvt<<<(int)(((size_t)Bb * Cc * Dd) / 2048), 256>>>(x, pXh);
    k_cvt<<<(Dd * HK) / 2048, 256>>>(Mq, pWq);
    k_cvt<<<(Dd * HK) / 2048, 256>>>(Mk, pWk);
    k_cvt<<<(int)(((size_t)Dd * HV) / 2048), 256>>>(Mv, pWv);

    // projections (natural layouts; consumers use flat-chunk addressing)
    k_projh<<<dim3(HK / 128, (Bb * Cc) / 128), 256, DSMP>>>(pXh, pWq, pPq, HK);
    k_projh<<<dim3(HK / 128, (Bb * Cc) / 128), 256, DSMP>>>(pXh, pWk, pPk, HK);
    k_projh<<<dim3(HV / 128, (Bb * Cc) / 128), 256, DSMP>>>(pXh, pWv, pPv, HV);

    k_sums<<<dim3(Cc / 128, Bb * 8), 256, DSMS>>>();
    k_fused<<<dim3(2, Bb * 8 * 8), 128, DSMF>>>(out);
}

// round 14
// speedup vs baseline: 5.7528x; 1.0287x over previous
#include <cuda_runtime.h>
#include <cuda_fp16.h>
#include <cstdint>

#define Bb 4
#define Cc 2048
#define Dd 1024
#define Kk 64
#define HK 512
#define HV 1024
#define Vd 128
#define Uu 256

#define STH 72                  // smem stride (halves), [m][k] tiles
#define TILEH (128 * STH)
#define VSTH 136                // smem stride (halves), [k][n] tiles
#define VTILEH (128 * VSTH)
#define BTILEH (64 * VSTH)      // 64-row [k][n] tile for k_projh

#define KE 0.18033688f          // 0.125 * log2(e)

// ---------------------------------------------------------------------------
// Scratch — natural layouts (R7-validated consumer addressing)
// ---------------------------------------------------------------------------
__device__ __align__(16) __half g_Xh[(size_t)Bb * Cc * Dd];       // 16 MB
__device__ __align__(16) __half g_Wq[(size_t)Dd * HK];
__device__ __align__(16) __half g_Wk[(size_t)Dd * HK];
__device__ __align__(16) __half g_Wv[(size_t)Dd * HV];
__device__ __align__(16) __half g_Pq[(size_t)Bb * Cc * HK];
__device__ __align__(16) __half g_Pk[(size_t)Bb * Cc * HK];
__device__ __align__(16) __half g_Pv[(size_t)Bb * Cc * HV];
__device__ __align__(16) float g_invD[Bb * 8 * Cc];   // holds -log2(D)

// ---------------------------------------------------------------------------
__device__ __forceinline__ uint32_t pack2(float x, float y) {
    __half2 h = __floats2half2_rn(x, y);
    return *reinterpret_cast<uint32_t*>(&h);
}

__device__ __forceinline__ float ex2(float x) {
    float y;
    asm("ex2.approx.f32 %0, %1;" : "=f"(y) : "f"(x));
    return y;
}

__device__ __forceinline__ void mma16(float* c, const uint32_t* a, const uint32_t* b) {
    asm volatile(
        "mma.sync.aligned.m16n8k16.row.col.f32.f16.f16.f32 "
        "{%0,%1,%2,%3}, {%4,%5,%6,%7}, {%8,%9}, {%0,%1,%2,%3};"
        : "+f"(c[0]), "+f"(c[1]), "+f"(c[2]), "+f"(c[3])
        : "r"(a[0]), "r"(a[1]), "r"(a[2]), "r"(a[3]), "r"(b[0]), "r"(b[1]));
}

__device__ __forceinline__ void ldm4(uint32_t* r, uint32_t addr) {
    asm volatile(
        "ldmatrix.sync.aligned.m8n8.x4.shared.b16 {%0,%1,%2,%3}, [%4];"
        : "=r"(r[0]), "=r"(r[1]), "=r"(r[2]), "=r"(r[3]) : "r"(addr));
}

__device__ __forceinline__ void ldm4t(uint32_t* r, uint32_t addr) {
    asm volatile(
        "ldmatrix.sync.aligned.m8n8.x4.trans.shared.b16 {%0,%1,%2,%3}, [%4];"
        : "=r"(r[0]), "=r"(r[1]), "=r"(r[2]), "=r"(r[3]) : "r"(addr));
}

__device__ __forceinline__ uint32_t s2u(const void* p) {
    return (uint32_t)__cvta_generic_to_shared(p);
}

__device__ __forceinline__ void cpa16(uint32_t d, const void* s) {
    asm volatile("cp.async.cg.shared.global [%0], [%1], 16;" :: "r"(d), "l"(s));
}
__device__ __forceinline__ void cp_commit() {
    asm volatile("cp.async.commit_group;");
}
template <int N> __device__ __forceinline__ void cp_wait() {
    asm volatile("cp.async.wait_group %0;" :: "n"(N));
}

// 64-deep k-tile warp mma, A [m][STH] via ldm4, B [n][SB] via ldm4.  (R7)
template <int SB>
__device__ __forceinline__ void warp_mma64(const __half* As, const __half* Bs,
                                           float acc[2][8][4],
                                           int wy, int wx, int lane) {
    const uint32_t ab = s2u(As), bb = s2u(Bs);
    const int arow = wy * 32 + (lane & 15);
    const int kA = (lane >> 4) << 3;
    const int brow = wx * 64 + (lane & 7) + ((lane >> 4) << 3);
    const int kB = ((lane >> 3) & 1) << 3;
#pragma unroll
    for (int ks = 0; ks < 4; ks++) {
        uint32_t a[2][4];
        ldm4(a[0], ab + (uint32_t)((arow * STH + ks * 16 + kA) * 2));
        ldm4(a[1], ab + (uint32_t)(((arow + 16) * STH + ks * 16 + kA) * 2));
#pragma unroll
        for (int j = 0; j < 4; j++) {
            uint32_t b[4];
            ldm4(b, bb + (uint32_t)(((brow + j * 16) * SB + ks * 16 + kB) * 2));
            mma16(acc[0][2 * j], a[0], b);
            mma16(acc[0][2 * j + 1], a[0], b + 2);
            mma16(acc[1][2 * j], a[1], b);
            mma16(acc[1][2 * j + 1], a[1], b + 2);
        }
    }
}

// 64-deep k-tile warp mma, A [m][STH] via ldm4, B natural [k][SB] via ldm4t.
template <int SB>
__device__ __forceinline__ void warp_mma64t(const __half* As, const __half* Bs,
                                            float acc[2][8][4],
                                            int wy, int wx, int lane) {
    const uint32_t ab = s2u(As), bb = s2u(Bs);
    const int arow = wy * 32 + (lane & 15);
    const int kA = (lane >> 4) << 3;
    const int vkrow = (lane & 7) + (((lane >> 3) & 1) << 3);
    const int vcol = (lane >> 4) << 3;
#pragma unroll
    for (int ks = 0; ks < 4; ks++) {
        uint32_t a[2][4];
        ldm4(a[0], ab + (uint32_t)((arow * STH + ks * 16 + kA) * 2));
        ldm4(a[1], ab + (uint32_t)(((arow + 16) * STH + ks * 16 + kA) * 2));
#pragma unroll
        for (int j = 0; j < 4; j++) {
            uint32_t b[4];
            ldm4t(b, bb + (uint32_t)(((ks * 16 + vkrow) * SB + wx * 64 + j * 16 + vcol) * 2));
            mma16(acc[0][2 * j], a[0], b);
            mma16(acc[0][2 * j + 1], a[0], b + 2);
            mma16(acc[1][2 * j], a[1], b);
            mma16(acc[1][2 * j + 1], a[1], b + 2);
        }
    }
}

// ---------------------------------------------------------------------------
// Merged convert kernel: all four fp32->fp16 conversions in one launch.
// Block ranges: x[0,4096) Mq[4096,4352) Mk[4352,4608) Mv[4608,5120)
// ---------------------------------------------------------------------------
__global__ void k_cvt_all(const float* __restrict__ x, const float* __restrict__ mq,
                          const float* __restrict__ mk, const float* __restrict__ mv,
                          __half* __restrict__ xh, __half* __restrict__ wq,
                          __half* __restrict__ wk, __half* __restrict__ wv) {
    int bid = blockIdx.x;
    const float* src;
    __half* dst;
    size_t off;
    if (bid < 4096)      { src = x;  dst = xh; off = (size_t)bid * 2048; }
    else if (bid < 4352) { src = mq; dst = wq; off = (size_t)(bid - 4096) * 2048; }
    else if (bid < 4608) { src = mk; dst = wk; off = (size_t)(bid - 4352) * 2048; }
    else                 { src = mv; dst = wv; off = (size_t)(bid - 4608) * 2048; }
    size_t i = off + (size_t)threadIdx.x * 8;
    float4 a = *(const float4*)(src + i);
    float4 b = *(const float4*)(src + i + 4);
    *(uint4*)(dst + i) = make_uint4(pack2(a.x, a.y), pack2(a.z, a.w),
                                    pack2(b.x, b.y), pack2(b.z, b.w));
}

// ---------------------------------------------------------------------------
// Kernel: half GEMM  P[8192,N] = Xh[8192,1024] @ Wh[1024,N]  (R11, validated)
// ---------------------------------------------------------------------------
extern __shared__ __align__(16) __half dsm[];

__global__ __launch_bounds__(256) void k_projh(const __half* __restrict__ X,
                                               const __half* __restrict__ W,
                                               __half* __restrict__ P, int N) {
    __half* Apb[2] = {dsm, dsm + TILEH};
    __half* Bpb[2] = {dsm + 2 * TILEH, dsm + 2 * TILEH + BTILEH};
    const int tid = threadIdx.x, lane = tid & 31, wid = tid >> 5;
    const int wy = wid & 3, wx = wid >> 2;
    const int m0 = blockIdx.y * 128, n0 = blockIdx.x * 128;

    float acc[2][8][4];
#pragma unroll
    for (int i = 0; i < 2; i++)
#pragma unroll
        for (int j = 0; j < 8; j++)
#pragma unroll
            for (int c = 0; c < 4; c++) acc[i][j][c] = 0.f;

    auto fill = [&](int k0, __half* a, __half* bs) {
#pragma unroll
        for (int p = 0; p < 4; p++) {
            int id = tid + 256 * p, r = id >> 3, c = id & 7;
            cpa16(s2u(a + r * STH + c * 8), X + (size_t)(m0 + r) * Dd + k0 + c * 8);
        }
#pragma unroll
        for (int p = 0; p < 4; p++) {
            int id = tid + 256 * p, r = id >> 4, c = id & 15;
            cpa16(s2u(bs + r * VSTH + c * 8), W + (size_t)(k0 + r) * N + n0 + c * 8);
        }
    };

    fill(0, Apb[0], Bpb[0]);
    cp_commit();

    const int NT = Dd / 64;
    for (int t = 0; t < NT; t++) {
        if (t + 1 < NT) {
            fill((t + 1) * 64, Apb[(t + 1) & 1], Bpb[(t + 1) & 1]);
            cp_commit();
            cp_wait<1>();
        } else {
            cp_wait<0>();
        }
        __syncthreads();
        warp_mma64t<VSTH>(Apb[t & 1], Bpb[t & 1], acc, wy, wx, lane);
        __syncthreads();
    }

    const int tg = lane & 3, rr = lane >> 2;
#pragma unroll
    for (int mf = 0; mf < 2; mf++) {
        int m = m0 + wy * 32 + mf * 16 + rr;
#pragma unroll
        for (int nf = 0; nf < 8; nf++) {
            int n = n0 + wx * 64 + nf * 8 + tg * 2;
            *(uint32_t*)(P + (size_t)m * N + n) = pack2(acc[mf][nf][0], acc[mf][nf][1]);
            *(uint32_t*)(P + (size_t)(m + 8) * N + n) = pack2(acc[mf][nf][2], acc[mf][nf][3]);
        }
    }
}

// ---------------------------------------------------------------------------
// Kernel 2: g_invD[z][c2] = -log2(sum_q exp(S/8)).  2 CTAs/SM for latency.
// ---------------------------------------------------------------------------
__global__ __launch_bounds__(256, 2) void k_sums() {
    __half* As = dsm;
    __half* Bs[2] = {dsm + TILEH, dsm + 2 * TILEH};
    float* sD = (float*)(dsm + 3 * TILEH);
    const int tid = threadIdx.x, lane = tid & 31, wid = tid >> 5;
    const int wy = wid & 3, wx = wid >> 2;
    const int tg = lane & 3, rr = lane >> 2;
    const int z = blockIdx.y;
    const int c20 = blockIdx.x * 128;
    const __half* Kh = g_Pk + (size_t)z * Cc * Kk;
    const __half* Qh = g_Pq + (size_t)z * Cc * Kk;

    if (tid < 128) sD[tid] = 0.f;

#pragma unroll
    for (int p = 0; p < 4; p++) {
        int id = tid + 256 * p, r = id >> 3, c = id & 7;
        cpa16(s2u(As + r * STH + c * 8), Kh + (size_t)(c20 + r) * Kk + c * 8);
        cpa16(s2u(Bs[0] + r * STH + c * 8), Qh + (size_t)r * Kk + c * 8);
    }
    cp_commit();

    float rs[2][2] = {{0.f, 0.f}, {0.f, 0.f}};
    const int NT = Cc / 128;
    for (int t = 0; t < NT; t++) {
        __syncthreads();
        if (t + 1 < NT) {
            const __half* src = Qh + (size_t)(t + 1) * 128 * Kk;
            __half* dst = Bs[(t + 1) & 1];
#pragma unroll
            for (int p = 0; p < 4; p++) {
                int id = tid + 256 * p, r = id >> 3, c = id & 7;
                cpa16(s2u(dst + r * STH + c * 8), src + (size_t)r * Kk + c * 8);
            }
            cp_commit();
            cp_wait<1>();
        } else {
            cp_wait<0>();
        }
        __syncthreads();

        float acc[2][8][4];
#pragma unroll
        for (int i = 0; i < 2; i++)
#pragma unroll
            for (int j = 0; j < 8; j++)
#pragma unroll
                for (int c = 0; c < 4; c++) acc[i][j][c] = 0.f;
        warp_mma64<STH>(As, Bs[t & 1], acc, wy, wx, lane);
#pragma unroll
        for (int mf = 0; mf < 2; mf++)
#pragma unroll
            for (int nf = 0; nf < 8; nf++) {
                rs[mf][0] += __expf(acc[mf][nf][0] * 0.125f)
                           + __expf(acc[mf][nf][1] * 0.125f);
                rs[mf][1] += __expf(acc[mf][nf][2] * 0.125f)
                           + __expf(acc[mf][nf][3] * 0.125f);
            }
    }
#pragma unroll
    for (int mf = 0; mf < 2; mf++)
#pragma unroll
        for (int h2 = 0; h2 < 2; h2++) {
            float s = rs[mf][h2];
            s += __shfl_xor_sync(0xffffffffu, s, 1);
            s += __shfl_xor_sync(0xffffffffu, s, 2);
            if (tg == 0)
                atomicAdd(&sD[wy * 32 + mf * 16 + h2 * 8 + rr], s);
        }
    __syncthreads();
    if (tid < 128) g_invD[z * Cc + c20 + tid] = -__log2f(sD[tid]);
}

// ---------------------------------------------------------------------------
// Kernel 3: fused scores+softmax+PV (R12 shape: 256 threads, 1 CTA per w,
// 32 u1/warp) with ex2/-log2 fused softmax scaling.
// ---------------------------------------------------------------------------
__global__ __launch_bounds__(256, 1) void k_fused(float* __restrict__ out) {
    __half* Ks[2] = {dsm, dsm + TILEH};
    __half* Vs[2] = {dsm + 2 * TILEH, dsm + 2 * TILEH + VTILEH};
    float* iDs[2] = {(float*)(dsm + 2 * TILEH + 2 * VTILEH),
                     (float*)(dsm + 2 * TILEH + 2 * VTILEH) + 128};
    const int tid = threadIdx.x, lane = tid & 31, wid = tid >> 5;
    const int tg = lane & 3, rr = lane >> 2;
    const int w = blockIdx.x;
    const int b = w >> 6, h = (w >> 3) & 7, hp = w & 7, z = w >> 3;
    const __half* Qh = g_Pq + (size_t)z * Cc * Kk;
    const __half* Kh = g_Pk + (size_t)z * Cc * Kk;
    const __half* Bv = g_Pv + (size_t)b * Cc * HV + (size_t)hp * Uu * HV;
    const float* iD = g_invD + z * Cc;

    const int u1b = wid * 32 + rr;
    const __half* Qbase = Qh + (size_t)(8 * u1b + hp) * Kk;
    uint32_t Qa[2][4][4];
#pragma unroll
    for (int mf = 0; mf < 2; mf++) {
        const __half* Q0 = Qbase + (size_t)(mf * 128) * Kk;
        const __half* Q1 = Q0 + (size_t)64 * Kk;
#pragma unroll
        for (int ks = 0; ks < 4; ks++) {
            Qa[mf][ks][0] = *(const uint32_t*)(Q0 + ks * 16 + 2 * tg);
            Qa[mf][ks][1] = *(const uint32_t*)(Q1 + ks * 16 + 2 * tg);
            Qa[mf][ks][2] = *(const uint32_t*)(Q0 + ks * 16 + 8 + 2 * tg);
            Qa[mf][ks][3] = *(const uint32_t*)(Q1 + ks * 16 + 8 + 2 * tg);
        }
    }

    float of[2][16][4];
#pragma unroll
    for (int mf = 0; mf < 2; mf++)
#pragma unroll
        for (int j = 0; j < 16; j++)
#pragma unroll
            for (int c = 0; c < 4; c++) of[mf][j][c] = 0.f;

    auto fill = [&](int c20, __half* ks, __half* vs, float* ids) {
#pragma unroll
        for (int p = 0; p < 4; p++) {
            int id = tid + 256 * p, r = id >> 3, c = id & 7;
            cpa16(s2u(ks + r * STH + c * 8), Kh + (size_t)(c20 + r) * Kk + c * 8);
        }
#pragma unroll
        for (int p = 0; p < 8; p++) {
            int id = tid + 256 * p, r = id >> 4, c = id & 15;
            cpa16(s2u(vs + r * VSTH + c * 8), Bv + (size_t)(c20 + r) * Vd + c * 8);
        }
        if (tid < 32) cpa16(s2u(ids + tid * 4), iD + c20 + tid * 4);
    };

    fill(0, Ks[0], Vs[0], iDs[0]);
    cp_commit();

    const int brow = (lane & 7) + ((lane >> 4) << 3);
    const int kB = ((lane >> 3) & 1) << 3;
    const int vkrow = (lane & 7) + (((lane >> 3) & 1) << 3);
    const int vcol = (lane >> 4) << 3;

    const int NT = Cc / 128;
    for (int t = 0; t < NT; t++) {
        __syncthreads();
        if (t + 1 < NT) {
            fill((t + 1) * 128, Ks[(t + 1) & 1], Vs[(t + 1) & 1], iDs[(t + 1) & 1]);
            cp_commit();
            cp_wait<1>();
        } else {
            cp_wait<0>();
        }
        __syncthreads();

        const uint32_t ksb = s2u(Ks[t & 1]), vsb = s2u(Vs[t & 1]);
        const float* ids = iDs[t & 1];

#pragma unroll
        for (int qtr = 0; qtr < 4; qtr++) {
            float cf[2][4][4];
#pragma unroll
            for (int mf = 0; mf < 2; mf++)
#pragma unroll
                for (int n = 0; n < 4; n++)
#pragma unroll
                    for (int c = 0; c < 4; c++) cf[mf][n][c] = 0.f;
#pragma unroll
            for (int ks = 0; ks < 4; ks++) {
#pragma unroll
                for (int jj = 0; jj < 2; jj++) {
                    int j = qtr * 2 + jj;
                    uint32_t bfr[4];
                    ldm4(bfr, ksb + (uint32_t)(((j * 16 + brow) * STH + ks * 16 + kB) * 2));
                    mma16(cf[0][2 * jj], Qa[0][ks], bfr);
                    mma16(cf[0][2 * jj + 1], Qa[0][ks], bfr + 2);
                    mma16(cf[1][2 * jj], Qa[1][ks], bfr);
                    mma16(cf[1][2 * jj + 1], Qa[1][ks], bfr + 2);
                }
            }

            uint32_t ak[2][2][4];
#pragma unroll
            for (int mf = 0; mf < 2; mf++)
#pragma unroll
                for (int nfl = 0; nfl < 4; nfl++) {
                    int nfg = qtr * 4 + nfl;
                    float2 Lv = *(const float2*)(ids + nfg * 8 + 2 * tg);
                    float e0 = ex2(fmaf(cf[mf][nfl][0], KE, Lv.x));
                    float e1 = ex2(fmaf(cf[mf][nfl][1], KE, Lv.y));
                    float e2 = ex2(fmaf(cf[mf][nfl][2], KE, Lv.x));
                    float e3 = ex2(fmaf(cf[mf][nfl][3], KE, Lv.y));
                    ak[mf][nfl >> 1][(nfl & 1) * 2 + 0] = pack2(e0, e1);
                    ak[mf][nfl >> 1][(nfl & 1) * 2 + 1] = pack2(e2, e3);
                }

#pragma unroll
            for (int kk = 0; kk < 2; kk++) {
                int kb = qtr * 2 + kk;
#pragma unroll
                for (int j = 0; j < 8; j++) {
                    uint32_t bfr[4];
                    ldm4t(bfr, vsb + (uint32_t)(((kb * 16 + vkrow) * VSTH + j * 16 + vcol) * 2));
                    mma16(of[0][2 * j], ak[0][kk], bfr);
                    mma16(of[0][2 * j + 1], ak[0][kk], bfr + 2);
                    mma16(of[1][2 * j], ak[1][kk], bfr);
                    mma16(of[1][2 * j + 1], ak[1][kk], bfr + 2);
                }
            }
        }
    }

#pragma unroll
    for (int mf = 0; mf < 2; mf++) {
        int u1 = wid * 32 + mf * 16 + rr;
        float* g0 = out + ((size_t)b * Cc + h * Uu + u1) * HV + hp * Vd;
        float* g1 = g0 + (size_t)8 * HV;
#pragma unroll
        for (int df = 0; df < 16; df++) {
            int d = df * 8 + 2 * tg;
            *(float2*)(g0 + d) = make_float2(of[mf][df][0], of[mf][df][1]);
            *(float2*)(g1 + d) = make_float2(of[mf][df][2], of[mf][df][3]);
        }
    }
}

// ---------------------------------------------------------------------------
extern "C" void kernel_launch(void* const* d_in, const int* in_sizes, int n_in,
                              void* d_out, int out_size) {
    (void)in_sizes; (void)n_in; (void)out_size;
    const float* x  = (const float*)d_in[0];
    const float* Mq = (const float*)d_in[1];
    const float* Mk = (const float*)d_in[2];
    const float* Mv = (const float*)d_in[3];
    float* out = (float*)d_out;

    __half *pXh, *pWq, *pWk, *pWv, *pPq, *pPk, *pPv;
    cudaGetSymbolAddress((void**)&pXh, g_Xh);
    cudaGetSymbolAddress((void**)&pWq, g_Wq);
    cudaGetSymbolAddress((void**)&pWk, g_Wk);
    cudaGetSymbolAddress((void**)&pWv, g_Wv);
    cudaGetSymbolAddress((void**)&pPq, g_Pq);
    cudaGetSymbolAddress((void**)&pPk, g_Pk);
    cudaGetSymbolAddress((void**)&pPv, g_Pv);

    const int DSMP = (2 * TILEH + 2 * BTILEH) * sizeof(__half);          // 71680
    const int DSMS = 3 * TILEH * sizeof(__half) + 512;                   // 55808
    const int DSMF = (2 * TILEH + 2 * VTILEH) * sizeof(__half) + 1024;   // 107520
    static bool attr_done = false;
    if (!attr_done) {
        cudaFuncSetAttribute(k_projh, cudaFuncAttributeMaxDynamicSharedMemorySize, DSMP);
        cudaFuncSetAttribute(k_sums, cudaFuncAttributeMaxDynamicSharedMemorySize, DSMS);
        cudaFuncSetAttribute(k_fused, cudaFuncAttributeMaxDynamicSharedMemorySize, DSMF);
        attr_done = true;
    }

    // merged convert pass (1 launch)
    k_cvt_all<<<5120, 256>>>(x, Mq, Mk, Mv, pXh, pWq, pWk, pWv);

    // projections (natural layouts; consumers use flat-chunk addressing)
    k_projh<<<dim3(HK / 128, (Bb * Cc) / 128), 256, DSMP>>>(pXh, pWq, pPq, HK);
    k_projh<<<dim3(HK / 128, (Bb * Cc) / 128), 256, DSMP>>>(pXh, pWk, pPk, HK);
    k_projh<<<dim3(HV / 128, (Bb * Cc) / 128), 256, DSMP>>>(pXh, pWv, pPv, HV);

    k_sums<<<dim3(Cc / 128, Bb * 8), 256, DSMS>>>();
    k_fused<<<Bb * 8 * 8, 256, DSMF>>>(out);
}